// round 4
// baseline (speedup 1.0000x reference)
#include <cuda_runtime.h>
#include <math.h>

#define N_NODES 50000
#define DIM     200
#define N_RELS  500
#define NHID    100
#define NHEADS  2
#define E_BASE  150000
#define E_NHOP  30000
#define E_ALL   180000

// ---------------- scratch (static device globals; no allocs) ----------------
__device__ float g_x[N_NODES * DIM];            // l2-normalized entities
__device__ float g_BcatA[600 * DIM];            // rows 0-399: Bcat1, 400-599: W_ent^T
__device__ float g_relproj1[NHEADS * N_RELS * NHID];
__device__ float g_projA[N_NODES * 600];        // cols 0-399: proj1, 400-599: entlin
__device__ int   g_dst[E_ALL];
__device__ int   g_src[E_ALL];
__device__ int   g_rA[E_ALL];
__device__ int   g_rB[E_ALL];
__device__ float g_x1[N_NODES * DIM];
__device__ float g_outrel[N_RELS * DIM];
__device__ float g_Bcat2[400 * DIM];
__device__ float g_relproj2[N_RELS * DIM];
__device__ float g_proj2[N_NODES * 400];
__device__ float g_mask[N_NODES];
// attention-scalar machinery
__device__ float g_w1[NHEADS * 600];            // per-head folded a^T a2 vectors
__device__ float g_w2[600];
__device__ float g_d1[NHEADS * N_NODES];
__device__ float g_s1[NHEADS * N_NODES];
__device__ float g_r1[NHEADS * N_RELS];
__device__ float g_d2[N_NODES];
__device__ float g_s2[N_NODES];
__device__ float g_r2[N_RELS];
__device__ float g_ev1[NHEADS * E_ALL];
__device__ float g_ev2[E_ALL];
// CSR by dst
__device__ int   g_cnt[N_NODES];
__device__ int   g_cur[N_NODES];
__device__ int   g_off[N_NODES + 1];
__device__ int   g_eidx[E_ALL];

// ---------------- small helpers ----------------
__device__ __forceinline__ float warp_sum(float v) {
    #pragma unroll
    for (int o = 16; o; o >>= 1) v += __shfl_xor_sync(0xFFFFFFFFu, v, o);
    return v;
}

// ---------------- zero small state ----------------
__global__ void zero_small() {
    int i = blockIdx.x * blockDim.x + threadIdx.x;
    if (i < N_NODES) { g_mask[i] = 0.f; g_cnt[i] = 0; }
}

// ---------------- build BcatA/Bcat2 + edge arrays + dst histogram ----------
__global__ void prep(const float* __restrict__ a_heads,
                     const float* __restrict__ a_out,
                     const float* __restrict__ W_ent,
                     const int* __restrict__ edge_list,
                     const int* __restrict__ edge_type,
                     const int* __restrict__ nhop) {
    int i = blockIdx.x * blockDim.x + threadIdx.x;
    if (i < 600 * DIM) {
        int j = i / DIM, k = i % DIM;
        float v;
        if (j < 400) {
            int h = j / 200, w = j % 200, sect = w / NHID, jr = w % NHID;
            v = a_heads[(h * NHID + jr) * 600 + sect * DIM + k];
        } else {
            v = W_ent[k * DIM + (j - 400)];       // W_ent^T
        }
        g_BcatA[i] = v;
        if (i < 400 * DIM)
            g_Bcat2[i] = a_out[(j % 200) * 600 + (j / 200) * DIM + k];
    }
    if (i < E_ALL) {
        int d;
        if (i < E_BASE) {
            d = edge_list[i];
            g_src[i] = edge_list[E_BASE + i];
            g_rA[i]  = edge_type[i];
            g_rB[i]  = -1;
        } else {
            int t = i - E_BASE;
            d = nhop[t * 4 + 3];
            g_src[i] = nhop[t * 4 + 0];
            g_rA[i]  = nhop[t * 4 + 1];
            g_rB[i]  = nhop[t * 4 + 2];
        }
        g_dst[i] = d;
        atomicAdd(&g_cnt[d], 1);
    }
}

// ---------------- exclusive scan of g_cnt -> g_off (single block) ----------
__global__ void scan_off() {
    __shared__ int sh[1024];
    const int CH = (N_NODES + 1023) / 1024;
    int t = threadIdx.x;
    int base = t * CH;
    int s = 0;
    for (int i = 0; i < CH; i++) { int idx = base + i; if (idx < N_NODES) s += g_cnt[idx]; }
    sh[t] = s; __syncthreads();
    for (int o = 1; o < 1024; o <<= 1) {
        int v = (t >= o) ? sh[t - o] : 0;
        __syncthreads();
        sh[t] += v;
        __syncthreads();
    }
    int run = sh[t] - s;                  // exclusive prefix for this chunk
    for (int i = 0; i < CH; i++) {
        int idx = base + i;
        if (idx < N_NODES) { g_off[idx] = run; run += g_cnt[idx]; g_cur[idx] = 0; }
    }
    if (t == 0) g_off[N_NODES] = E_ALL;
}

__global__ void scatter_eidx() {
    int e = blockIdx.x * blockDim.x + threadIdx.x;
    if (e >= E_ALL) return;
    int d = g_dst[e];
    int pos = g_off[d] + atomicAdd(&g_cur[d], 1);
    g_eidx[pos] = e;
}

__global__ void mask_scatter(const int* __restrict__ batch, int n) {
    int i = blockIdx.x * blockDim.x + threadIdx.x;
    if (i < n) g_mask[batch[i]] = 1.0f;
}

// ---------------- row-wise l2 norm into g_x ----------------
__global__ void l2norm_entities(const float* __restrict__ in) {
    int w = (blockIdx.x * blockDim.x + threadIdx.x) >> 5;
    int lane = threadIdx.x & 31;
    if (w >= N_NODES) return;
    const float* r = in + (size_t)w * DIM;
    float ss = 0.f;
    for (int j = lane; j < DIM; j += 32) { float v = r[j]; ss += v * v; }
    ss = warp_sum(ss);
    float sc = 1.f / fmaxf(sqrtf(ss), 1e-12f);
    for (int j = lane; j < DIM; j += 32) g_x[(size_t)w * DIM + j] = r[j] * sc;
}

// ---------------- folded attention vectors ----------------
// w1[h][k] = sum_j a_heads[h,j,k] * a2h[h,j]   (k < 600)
// w2[k]    = sum_j a_out[j,k]     * a2o[j]
__global__ void fold_w(const float* __restrict__ a_heads, const float* __restrict__ a2_h,
                       const float* __restrict__ a_out,   const float* __restrict__ a2_o) {
    int i = blockIdx.x * blockDim.x + threadIdx.x;
    if (i < NHEADS * 600) {
        int h = i / 600, k = i % 600;
        float s = 0.f;
        for (int j = 0; j < NHID; j++) s += a_heads[(h * NHID + j) * 600 + k] * a2_h[h * NHID + j];
        g_w1[i] = s;
    }
    if (i < 600) {
        float s = 0.f;
        for (int j = 0; j < 200; j++) s += a_out[j * 600 + i] * a2_o[j];
        g_w2[i] = s;
    }
}

// ---------------- relation projections ----------------
__global__ void relproj1_k(const float* __restrict__ rel, const float* __restrict__ a_heads) {
    int i = blockIdx.x * blockDim.x + threadIdx.x;
    if (i >= NHEADS * N_RELS * NHID) return;
    int h = i / (N_RELS * NHID);
    int rem = i % (N_RELS * NHID);
    int r = rem / NHID, j = rem % NHID;
    const float* ar = a_heads + (h * NHID + j) * 600 + 400;
    const float* rr = rel + r * DIM;
    float s = 0.f;
    #pragma unroll 4
    for (int k = 0; k < DIM; k++) s += rr[k] * ar[k];
    g_relproj1[i] = s;
}

__global__ void outrel_k(const float* __restrict__ rel, const float* __restrict__ W_gat) {
    int i = blockIdx.x * blockDim.x + threadIdx.x;
    if (i >= N_RELS * DIM) return;
    int r = i / DIM, j = i % DIM;
    const float* rr = rel + r * DIM;
    float s = 0.f;
    #pragma unroll 4
    for (int k = 0; k < DIM; k++) s += rr[k] * W_gat[k * DIM + j];
    g_outrel[i] = s;
}

__global__ void relproj2_k(const float* __restrict__ a_out) {
    int i = blockIdx.x * blockDim.x + threadIdx.x;
    if (i >= N_RELS * DIM) return;
    int r = i / DIM, j = i % DIM;
    const float* rr = g_outrel + r * DIM;
    const float* ar = a_out + j * 600 + 400;
    float s = 0.f;
    #pragma unroll 4
    for (int k = 0; k < DIM; k++) s += rr[k] * ar[k];
    g_relproj2[i] = s;
}

// ---------------- per-node / per-rel attention scalars ----------------
__global__ void node_scalars1() {
    int n = (blockIdx.x * blockDim.x + threadIdx.x) >> 5;
    int lane = threadIdx.x & 31;
    if (n >= N_NODES) return;
    float a = 0.f, b = 0.f, c = 0.f, d = 0.f;
    for (int j = lane; j < DIM; j += 32) {
        float xv = g_x[(size_t)n * DIM + j];
        a += xv * g_w1[j];            // h0 dst
        b += xv * g_w1[200 + j];      // h0 src
        c += xv * g_w1[600 + j];      // h1 dst
        d += xv * g_w1[800 + j];      // h1 src
    }
    a = warp_sum(a); b = warp_sum(b); c = warp_sum(c); d = warp_sum(d);
    if (lane == 0) {
        g_d1[n] = a; g_s1[n] = b;
        g_d1[N_NODES + n] = c; g_s1[N_NODES + n] = d;
    }
}

__global__ void node_scalars2() {
    int n = (blockIdx.x * blockDim.x + threadIdx.x) >> 5;
    int lane = threadIdx.x & 31;
    if (n >= N_NODES) return;
    float a = 0.f, b = 0.f;
    for (int j = lane; j < DIM; j += 32) {
        float xv = g_x1[(size_t)n * DIM + j];
        a += xv * g_w2[j];
        b += xv * g_w2[200 + j];
    }
    a = warp_sum(a); b = warp_sum(b);
    if (lane == 0) { g_d2[n] = a; g_s2[n] = b; }
}

__global__ void rel_scalars(const float* __restrict__ rel) {
    int i = blockIdx.x * blockDim.x + threadIdx.x;
    if (i < NHEADS * N_RELS) {
        int h = i / N_RELS, r = i % N_RELS;
        float s = 0.f;
        for (int k = 0; k < DIM; k++) s += rel[r * DIM + k] * g_w1[h * 600 + 400 + k];
        g_r1[i] = s;
    }
    if (i < N_RELS) {
        float s = 0.f;
        for (int k = 0; k < DIM; k++) s += g_outrel[i * DIM + k] * g_w2[400 + k];
        g_r2[i] = s;
    }
}

// ---------------- edge logits (scalar gathers only) ----------------
__global__ void edge_logits1() {
    int e = blockIdx.x * blockDim.x + threadIdx.x;
    if (e >= E_ALL) return;
    int d = g_dst[e], s = g_src[e], ra = g_rA[e], rb = g_rB[e];
    #pragma unroll
    for (int h = 0; h < NHEADS; h++) {
        float dot = g_d1[h * N_NODES + d] + g_s1[h * N_NODES + s] + g_r1[h * N_RELS + ra];
        if (rb >= 0) dot += g_r1[h * N_RELS + rb];
        float lr = dot > 0.f ? dot : 0.2f * dot;
        g_ev1[h * E_ALL + e] = __expf(-lr);
    }
}

__global__ void edge_logits2() {
    int e = blockIdx.x * blockDim.x + threadIdx.x;
    if (e >= E_ALL) return;
    float dot = g_d2[g_dst[e]] + g_s2[g_src[e]] + g_r2[g_rA[e]];
    int rb = g_rB[e];
    if (rb >= 0) dot += g_r2[rb];
    float lr = dot > 0.f ? dot : 0.2f * dot;
    g_ev2[e] = __expf(-lr);
}

// ---------------- 128x128 register-blocked SGEMM: C = A[M,K] * B[Nn,K]^T ----
#define BM 128
#define BN 128
#define BK 8
#define SPAD 4

template <int SEL>
__global__ __launch_bounds__(256) void sgemm128() {
    const float* A; const float* B; float* C; int M, Nn;
    if (SEL == 0) { A = g_x;  B = g_BcatA; C = g_projA; M = N_NODES; Nn = 600; }
    else          { A = g_x1; B = g_Bcat2; C = g_proj2; M = N_NODES; Nn = 400; }
    const int K = DIM;

    __shared__ float As[BK][BM + SPAD];
    __shared__ float Bs[BK][BN + SPAD];

    int tid  = threadIdx.x;
    int lrow = tid >> 1;
    int lk4  = (tid & 1) * 4;
    int row0 = blockIdx.y * BM;
    int col0 = blockIdx.x * BN;
    int tx = tid % 16, ty = tid / 16;

    const float* Aptr = A + (size_t)(row0 + lrow) * K + lk4;
    const float* Bptr = B + (size_t)(col0 + lrow) * K + lk4;
    bool aok = (row0 + lrow) < M;
    bool bok = (col0 + lrow) < Nn;

    float4 av = aok ? *(const float4*)Aptr : make_float4(0.f, 0.f, 0.f, 0.f);
    float4 bv = bok ? *(const float4*)Bptr : make_float4(0.f, 0.f, 0.f, 0.f);

    float acc[8][8] = {};

    for (int k0 = 0; k0 < K; k0 += BK) {
        As[lk4 + 0][lrow] = av.x; As[lk4 + 1][lrow] = av.y;
        As[lk4 + 2][lrow] = av.z; As[lk4 + 3][lrow] = av.w;
        Bs[lk4 + 0][lrow] = bv.x; Bs[lk4 + 1][lrow] = bv.y;
        Bs[lk4 + 2][lrow] = bv.z; Bs[lk4 + 3][lrow] = bv.w;
        __syncthreads();

        if (k0 + BK < K) {
            av = aok ? *(const float4*)(Aptr + k0 + BK) : make_float4(0.f, 0.f, 0.f, 0.f);
            bv = bok ? *(const float4*)(Bptr + k0 + BK) : make_float4(0.f, 0.f, 0.f, 0.f);
        }

        #pragma unroll
        for (int k = 0; k < BK; k++) {
            float4 a0 = *(const float4*)&As[k][ty * 8];
            float4 a1 = *(const float4*)&As[k][ty * 8 + 4];
            float4 b0 = *(const float4*)&Bs[k][tx * 8];
            float4 b1 = *(const float4*)&Bs[k][tx * 8 + 4];
            float ar[8] = {a0.x, a0.y, a0.z, a0.w, a1.x, a1.y, a1.z, a1.w};
            float br[8] = {b0.x, b0.y, b0.z, b0.w, b1.x, b1.y, b1.z, b1.w};
            #pragma unroll
            for (int i = 0; i < 8; i++)
                #pragma unroll
                for (int j = 0; j < 8; j++)
                    acc[i][j] += ar[i] * br[j];
        }
        __syncthreads();
    }

    #pragma unroll
    for (int i = 0; i < 8; i++) {
        int gr = row0 + ty * 8 + i;
        if (gr >= M) continue;
        float* crow = C + (size_t)gr * Nn;
        int gc0 = col0 + tx * 8;
        if (gc0 < Nn)
            *(float4*)(crow + gc0) = make_float4(acc[i][0], acc[i][1], acc[i][2], acc[i][3]);
        if (gc0 + 4 < Nn)
            *(float4*)(crow + gc0 + 4) = make_float4(acc[i][4], acc[i][5], acc[i][6], acc[i][7]);
    }
}

// ---------------- layer-1 aggregation (warp per node, both heads) ----------
// x1[n] = elu(pd + (sum_e ev*(ps[src]+rp))/sum_e ev), 0 if degree 0
__global__ void agg1() {
    int n = (blockIdx.x * blockDim.x + threadIdx.x) >> 5;
    int lane = threadIdx.x & 31;
    if (n >= N_NODES) return;
    int beg = g_off[n], end = g_off[n + 1];
    float acc0[4] = {}, acc1[4] = {};
    float S0 = 0.f, S1 = 0.f;
    for (int p = beg; p < end; p++) {
        int e = g_eidx[p];
        int s = g_src[e], ra = g_rA[e], rb = g_rB[e];
        float e0 = g_ev1[e], e1 = g_ev1[E_ALL + e];
        S0 += e0; S1 += e1;
        const float* ps = g_projA + (size_t)s * 600;
        const float* r0 = g_relproj1 + ra * NHID;
        const float* r1 = g_relproj1 + (N_RELS + ra) * NHID;
        const float* r0b = (rb >= 0) ? g_relproj1 + rb * NHID : nullptr;
        const float* r1b = (rb >= 0) ? g_relproj1 + (N_RELS + rb) * NHID : nullptr;
        #pragma unroll
        for (int t = 0; t < 4; t++) {
            int j = lane + 32 * t;
            if (j < NHID) {
                float v0 = ps[100 + j] + r0[j];
                float v1 = ps[300 + j] + r1[j];
                if (rb >= 0) { v0 += r0b[j]; v1 += r1b[j]; }
                acc0[t] += e0 * v0;
                acc1[t] += e1 * v1;
            }
        }
    }
    bool has = end > beg;
    float i0 = has ? 1.f / S0 : 0.f;
    float i1 = has ? 1.f / S1 : 0.f;
    const float* pd = g_projA + (size_t)n * 600;
    float* xr = g_x1 + (size_t)n * DIM;
    #pragma unroll
    for (int t = 0; t < 4; t++) {
        int j = lane + 32 * t;
        if (j < NHID) {
            float hp0 = has ? pd[j] + acc0[t] * i0 : 0.f;
            float hp1 = has ? pd[200 + j] + acc1[t] * i1 : 0.f;
            xr[j]       = hp0 > 0.f ? hp0 : (__expf(hp0) - 1.f);
            xr[100 + j] = hp1 > 0.f ? hp1 : (__expf(hp1) - 1.f);
        }
    }
}

// ---------------- layer-2 aggregation fused with finalize ----------------
__global__ void agg2_finalize(float* __restrict__ out) {
    int n = (blockIdx.x * blockDim.x + threadIdx.x) >> 5;
    int lane = threadIdx.x & 31;
    if (n >= N_NODES) return;
    int beg = g_off[n], end = g_off[n + 1];
    float acc[7] = {};
    float S = 0.f;
    for (int p = beg; p < end; p++) {
        int e = g_eidx[p];
        int s = g_src[e], ra = g_rA[e], rb = g_rB[e];
        float ev = g_ev2[e];
        S += ev;
        const float* ps = g_proj2 + (size_t)s * 400 + 200;
        const float* rp = g_relproj2 + ra * DIM;
        const float* rpb = (rb >= 0) ? g_relproj2 + rb * DIM : nullptr;
        #pragma unroll
        for (int t = 0; t < 7; t++) {
            int j = lane + 32 * t;
            if (j < DIM) {
                float v = ps[j] + rp[j];
                if (rb >= 0) v += rpb[j];
                acc[t] += ev * v;
            }
        }
    }
    bool has = end > beg;
    float iS = has ? 1.f / S : 0.f;
    float mk = g_mask[n];
    const float* pd = g_proj2 + (size_t)n * 400;
    const float* lin = g_projA + (size_t)n * 600 + 400;
    float v[7];
    float ss = 0.f;
    #pragma unroll
    for (int t = 0; t < 7; t++) {
        int j = lane + 32 * t;
        float val = 0.f;
        if (j < DIM) {
            float hp = has ? pd[j] + acc[t] * iS : 0.f;
            float el = hp > 0.f ? hp : (expf(hp) - 1.f);
            val = lin[j] + mk * el;
            ss += val * val;
        }
        v[t] = val;
    }
    ss = warp_sum(ss);
    float sc = 1.f / fmaxf(sqrtf(ss), 1e-12f);
    #pragma unroll
    for (int t = 0; t < 7; t++) {
        int j = lane + 32 * t;
        if (j < DIM) out[(size_t)n * DIM + j] = v[t] * sc;
    }
}

__global__ void copy_tail(float* __restrict__ out) {
    int i = blockIdx.x * blockDim.x + threadIdx.x;
    const size_t base = (size_t)N_NODES * DIM;
    if (i < N_RELS * DIM) out[base + i] = g_outrel[i];
    if (i < N_NODES) out[base + N_RELS * DIM + i] = g_mask[i];
}

// ---------------- launch ----------------
extern "C" void kernel_launch(void* const* d_in, const int* in_sizes, int n_in,
                              void* d_out, int out_size) {
    const float* ent   = (const float*)d_in[0];
    const float* rel   = (const float*)d_in[1];
    const float* W_ent = (const float*)d_in[2];
    const float* W_gat = (const float*)d_in[3];
    const float* a_h   = (const float*)d_in[4];
    const float* a2_h  = (const float*)d_in[5];
    const float* a_o   = (const float*)d_in[6];
    const float* a2_o  = (const float*)d_in[7];
    const int*   batch = (const int*)d_in[8];
    const int*   elist = (const int*)d_in[9];
    const int*   etype = (const int*)d_in[10];
    const int*   nhop  = (const int*)d_in[11];
    float* out = (float*)d_out;
    int n_batch = in_sizes[8];

    zero_small<<<(N_NODES + 255) / 256, 256>>>();
    prep<<<(E_ALL + 255) / 256, 256>>>(a_h, a_o, W_ent, elist, etype, nhop);
    scan_off<<<1, 1024>>>();
    scatter_eidx<<<(E_ALL + 255) / 256, 256>>>();
    mask_scatter<<<(n_batch + 255) / 256, 256>>>(batch, n_batch);
    l2norm_entities<<<(N_NODES * 32 + 255) / 256, 256>>>(ent);
    fold_w<<<(NHEADS * 600 + 255) / 256, 256>>>(a_h, a2_h, a_o, a2_o);
    relproj1_k<<<(NHEADS * N_RELS * NHID + 255) / 256, 256>>>(rel, a_h);
    outrel_k<<<(N_RELS * DIM + 255) / 256, 256>>>(rel, W_gat);
    relproj2_k<<<(N_RELS * DIM + 255) / 256, 256>>>(a_o);
    rel_scalars<<<(NHEADS * N_RELS + 255) / 256, 256>>>(rel);
    node_scalars1<<<(N_NODES * 32 + 255) / 256, 256>>>();
    edge_logits1<<<(E_ALL + 255) / 256, 256>>>();

    {   // projA = [x@Bcat1^T | x@W_ent]  (N=600)
        dim3 grid((600 + BN - 1) / BN, (N_NODES + BM - 1) / BM);
        sgemm128<0><<<grid, 256>>>();
    }

    agg1<<<(N_NODES * 32 + 255) / 256, 256>>>();

    node_scalars2<<<(N_NODES * 32 + 255) / 256, 256>>>();
    edge_logits2<<<(E_ALL + 255) / 256, 256>>>();

    {   // proj2 = x1 @ Bcat2^T  (N=400)
        dim3 grid((400 + BN - 1) / BN, (N_NODES + BM - 1) / BM);
        sgemm128<1><<<grid, 256>>>();
    }

    agg2_finalize<<<(N_NODES * 32 + 255) / 256, 256>>>(out);
    copy_tail<<<(N_RELS * DIM + 255) / 256, 256>>>(out);
}

// round 5
// speedup vs baseline: 1.2203x; 1.2203x over previous
#include <cuda_runtime.h>
#include <math.h>

#define N_NODES 50000
#define DIM     200
#define N_RELS  500
#define NHID    100
#define NHEADS  2
#define E_BASE  150000
#define E_NHOP  30000
#define E_ALL   180000

typedef unsigned long long u64;

// ---------------- scratch (static device globals; no allocs) ----------------
__device__ float g_x[N_NODES * DIM];            // l2-normalized entities
__device__ float g_BcatA[600 * DIM];            // rows 0-399: Bcat1, 400-599: W_ent^T
__device__ float g_relproj1[NHEADS * N_RELS * NHID];
__device__ float g_projA[N_NODES * 600];        // cols 0-399: proj1, 400-599: entlin
__device__ int   g_dst[E_ALL];
__device__ int   g_src[E_ALL];
__device__ int   g_rA[E_ALL];
__device__ int   g_rB[E_ALL];
__device__ float g_rowsum1[NHEADS * N_NODES];
__device__ float g_acc1[NHEADS * N_NODES * NHID];
__device__ float g_x1[N_NODES * DIM];
__device__ float g_outrel[N_RELS * DIM];
__device__ float g_Bcat2[400 * DIM];
__device__ float g_relproj2[N_RELS * DIM];
__device__ float g_proj2[N_NODES * 400];
__device__ float g_rowsum2[N_NODES];
__device__ float g_acc2[N_NODES * DIM];
__device__ float g_mask[N_NODES];
// attention-scalar machinery
__device__ float g_w1[NHEADS * 600];            // per-head folded a^T a2 vectors
__device__ float g_w2[600];
__device__ float g_d1[NHEADS * N_NODES];
__device__ float g_s1[NHEADS * N_NODES];
__device__ float g_r1[NHEADS * N_RELS];
__device__ float g_d2[N_NODES];
__device__ float g_s2[N_NODES];
__device__ float g_r2[N_RELS];

// ---------------- small helpers ----------------
__device__ __forceinline__ float warp_sum(float v) {
    #pragma unroll
    for (int o = 16; o; o >>= 1) v += __shfl_xor_sync(0xFFFFFFFFu, v, o);
    return v;
}

__device__ __forceinline__ u64 pack2(float lo, float hi) {
    u64 r; asm("mov.b64 %0, {%1, %2};" : "=l"(r) : "f"(lo), "f"(hi)); return r;
}
__device__ __forceinline__ void unpack2(u64 v, float& lo, float& hi) {
    asm("mov.b64 {%0, %1}, %2;" : "=f"(lo), "=f"(hi) : "l"(v));
}
__device__ __forceinline__ void ffma2(u64& d, u64 a, u64 b) {
    asm("fma.rn.f32x2 %0, %1, %2, %0;" : "+l"(d) : "l"(a), "l"(b));
}

// ---------------- zero accumulators ----------------
__global__ void zero_all() {
    int stride = gridDim.x * blockDim.x;
    for (int i = blockIdx.x * blockDim.x + threadIdx.x;
         i < NHEADS * N_NODES * NHID; i += stride) {
        g_acc1[i] = 0.f;
        if (i < N_NODES * DIM) g_acc2[i] = 0.f;
        if (i < NHEADS * N_NODES) g_rowsum1[i] = 0.f;
        if (i < N_NODES) { g_rowsum2[i] = 0.f; g_mask[i] = 0.f; }
    }
}

// ---------------- build BcatA/Bcat2 + edge arrays ----------------
__global__ void prep(const float* __restrict__ a_heads,
                     const float* __restrict__ a_out,
                     const float* __restrict__ W_ent,
                     const int* __restrict__ edge_list,
                     const int* __restrict__ edge_type,
                     const int* __restrict__ nhop) {
    int i = blockIdx.x * blockDim.x + threadIdx.x;
    if (i < 600 * DIM) {
        int j = i / DIM, k = i % DIM;
        float v;
        if (j < 400) {
            int h = j / 200, w = j % 200, sect = w / NHID, jr = w % NHID;
            v = a_heads[(h * NHID + jr) * 600 + sect * DIM + k];
        } else {
            v = W_ent[k * DIM + (j - 400)];       // W_ent^T
        }
        g_BcatA[i] = v;
        if (i < 400 * DIM)
            g_Bcat2[i] = a_out[(j % 200) * 600 + (j / 200) * DIM + k];
    }
    if (i < E_ALL) {
        if (i < E_BASE) {
            g_dst[i] = edge_list[i];
            g_src[i] = edge_list[E_BASE + i];
            g_rA[i]  = edge_type[i];
            g_rB[i]  = -1;
        } else {
            int t = i - E_BASE;
            g_dst[i] = nhop[t * 4 + 3];
            g_src[i] = nhop[t * 4 + 0];
            g_rA[i]  = nhop[t * 4 + 1];
            g_rB[i]  = nhop[t * 4 + 2];
        }
    }
}

__global__ void mask_scatter(const int* __restrict__ batch, int n) {
    int i = blockIdx.x * blockDim.x + threadIdx.x;
    if (i < n) g_mask[batch[i]] = 1.0f;
}

// ---------------- folded attention vectors ----------------
__global__ void fold_w(const float* __restrict__ a_heads, const float* __restrict__ a2_h,
                       const float* __restrict__ a_out,   const float* __restrict__ a2_o) {
    int i = blockIdx.x * blockDim.x + threadIdx.x;
    if (i < NHEADS * 600) {
        int h = i / 600, k = i % 600;
        float s = 0.f;
        for (int j = 0; j < NHID; j++) s += a_heads[(h * NHID + j) * 600 + k] * a2_h[h * NHID + j];
        g_w1[i] = s;
    }
    if (i < 600) {
        float s = 0.f;
        for (int j = 0; j < 200; j++) s += a_out[j * 600 + i] * a2_o[j];
        g_w2[i] = s;
    }
}

// ---------------- l2 norm + layer-1 node attention scalars (fused) --------
__global__ void l2norm_scalars(const float* __restrict__ in) {
    int n = (blockIdx.x * blockDim.x + threadIdx.x) >> 5;
    int lane = threadIdx.x & 31;
    if (n >= N_NODES) return;
    const float* r = in + (size_t)n * DIM;
    float v[7];
    float ss = 0.f;
    #pragma unroll
    for (int t = 0; t < 7; t++) {
        int j = lane + 32 * t;
        float x = (j < DIM) ? r[j] : 0.f;
        v[t] = x; ss += x * x;
    }
    ss = warp_sum(ss);
    float sc = 1.f / fmaxf(sqrtf(ss), 1e-12f);
    float a = 0.f, b = 0.f, c = 0.f, d = 0.f;
    #pragma unroll
    for (int t = 0; t < 7; t++) {
        int j = lane + 32 * t;
        if (j < DIM) {
            float xv = v[t] * sc;
            g_x[(size_t)n * DIM + j] = xv;
            a += xv * g_w1[j];
            b += xv * g_w1[200 + j];
            c += xv * g_w1[600 + j];
            d += xv * g_w1[800 + j];
        }
    }
    a = warp_sum(a); b = warp_sum(b); c = warp_sum(c); d = warp_sum(d);
    if (lane == 0) {
        g_d1[n] = a; g_s1[n] = b;
        g_d1[N_NODES + n] = c; g_s1[N_NODES + n] = d;
    }
}

// ---------------- relation projections ----------------
__global__ void relproj1_k(const float* __restrict__ rel, const float* __restrict__ a_heads) {
    int i = blockIdx.x * blockDim.x + threadIdx.x;
    if (i >= NHEADS * N_RELS * NHID) return;
    int h = i / (N_RELS * NHID);
    int rem = i % (N_RELS * NHID);
    int r = rem / NHID, j = rem % NHID;
    const float* ar = a_heads + (h * NHID + j) * 600 + 400;
    const float* rr = rel + r * DIM;
    float s = 0.f;
    #pragma unroll 4
    for (int k = 0; k < DIM; k++) s += rr[k] * ar[k];
    g_relproj1[i] = s;
}

__global__ void outrel_k(const float* __restrict__ rel, const float* __restrict__ W_gat) {
    int i = blockIdx.x * blockDim.x + threadIdx.x;
    if (i >= N_RELS * DIM) return;
    int r = i / DIM, j = i % DIM;
    const float* rr = rel + r * DIM;
    float s = 0.f;
    #pragma unroll 4
    for (int k = 0; k < DIM; k++) s += rr[k] * W_gat[k * DIM + j];
    g_outrel[i] = s;
}

__global__ void relproj2_k(const float* __restrict__ a_out) {
    int i = blockIdx.x * blockDim.x + threadIdx.x;
    if (i >= N_RELS * DIM) return;
    int r = i / DIM, j = i % DIM;
    const float* rr = g_outrel + r * DIM;
    const float* ar = a_out + j * 600 + 400;
    float s = 0.f;
    #pragma unroll 4
    for (int k = 0; k < DIM; k++) s += rr[k] * ar[k];
    g_relproj2[i] = s;
}

__global__ void rel_scalars(const float* __restrict__ rel) {
    int i = blockIdx.x * blockDim.x + threadIdx.x;
    if (i < NHEADS * N_RELS) {
        int h = i / N_RELS, r = i % N_RELS;
        float s = 0.f;
        for (int k = 0; k < DIM; k++) s += rel[r * DIM + k] * g_w1[h * 600 + 400 + k];
        g_r1[i] = s;
    }
    if (i < N_RELS) {
        float s = 0.f;
        for (int k = 0; k < DIM; k++) s += g_outrel[i * DIM + k] * g_w2[400 + k];
        g_r2[i] = s;
    }
}

// ---------------- 128x128 SGEMM with packed fp32x2 FMA ----------------
#define BM 128
#define BN 128
#define BK 8
#define SPAD 4

template <int SEL>
__global__ __launch_bounds__(256) void sgemm128() {
    const float* A; const float* B; float* C; int M, Nn;
    if (SEL == 0) { A = g_x;  B = g_BcatA; C = g_projA; M = N_NODES; Nn = 600; }
    else          { A = g_x1; B = g_Bcat2; C = g_proj2; M = N_NODES; Nn = 400; }
    const int K = DIM;

    __shared__ __align__(16) float As[BK][BM + SPAD];
    __shared__ __align__(16) float Bs[BK][BN + SPAD];

    int tid  = threadIdx.x;
    int lrow = tid >> 1;
    int lk4  = (tid & 1) * 4;
    int row0 = blockIdx.y * BM;
    int col0 = blockIdx.x * BN;
    int tx = tid % 16, ty = tid / 16;

    const float* Aptr = A + (size_t)(row0 + lrow) * K + lk4;
    const float* Bptr = B + (size_t)(col0 + lrow) * K + lk4;
    bool aok = (row0 + lrow) < M;
    bool bok = (col0 + lrow) < Nn;

    float4 av = aok ? *(const float4*)Aptr : make_float4(0.f, 0.f, 0.f, 0.f);
    float4 bv = bok ? *(const float4*)Bptr : make_float4(0.f, 0.f, 0.f, 0.f);

    u64 acc[8][4];
    #pragma unroll
    for (int i = 0; i < 8; i++)
        #pragma unroll
        for (int p = 0; p < 4; p++) acc[i][p] = 0ull;

    for (int k0 = 0; k0 < K; k0 += BK) {
        As[lk4 + 0][lrow] = av.x; As[lk4 + 1][lrow] = av.y;
        As[lk4 + 2][lrow] = av.z; As[lk4 + 3][lrow] = av.w;
        Bs[lk4 + 0][lrow] = bv.x; Bs[lk4 + 1][lrow] = bv.y;
        Bs[lk4 + 2][lrow] = bv.z; Bs[lk4 + 3][lrow] = bv.w;
        __syncthreads();

        if (k0 + BK < K) {
            av = aok ? *(const float4*)(Aptr + k0 + BK) : make_float4(0.f, 0.f, 0.f, 0.f);
            bv = bok ? *(const float4*)(Bptr + k0 + BK) : make_float4(0.f, 0.f, 0.f, 0.f);
        }

        #pragma unroll
        for (int k = 0; k < BK; k++) {
            float4 a0 = *(const float4*)&As[k][ty * 8];
            float4 a1 = *(const float4*)&As[k][ty * 8 + 4];
            const u64* brow = (const u64*)&Bs[k][tx * 8];
            u64 bp[4];
            #pragma unroll
            for (int p = 0; p < 4; p++) bp[p] = brow[p];
            u64 ap[8];
            ap[0] = pack2(a0.x, a0.x); ap[1] = pack2(a0.y, a0.y);
            ap[2] = pack2(a0.z, a0.z); ap[3] = pack2(a0.w, a0.w);
            ap[4] = pack2(a1.x, a1.x); ap[5] = pack2(a1.y, a1.y);
            ap[6] = pack2(a1.z, a1.z); ap[7] = pack2(a1.w, a1.w);
            #pragma unroll
            for (int i = 0; i < 8; i++)
                #pragma unroll
                for (int p = 0; p < 4; p++)
                    ffma2(acc[i][p], ap[i], bp[p]);
        }
        __syncthreads();
    }

    #pragma unroll
    for (int i = 0; i < 8; i++) {
        int gr = row0 + ty * 8 + i;
        if (gr >= M) continue;
        float* crow = C + (size_t)gr * Nn;
        int gc0 = col0 + tx * 8;
        float c0, c1, c2, c3, c4, c5, c6, c7;
        unpack2(acc[i][0], c0, c1); unpack2(acc[i][1], c2, c3);
        unpack2(acc[i][2], c4, c5); unpack2(acc[i][3], c6, c7);
        if (gc0 < Nn)     *(float4*)(crow + gc0)     = make_float4(c0, c1, c2, c3);
        if (gc0 + 4 < Nn) *(float4*)(crow + gc0 + 4) = make_float4(c4, c5, c6, c7);
    }
}

// ---------------- edge scatter, layer 1 (warp per edge, head = blockIdx.y) --
__global__ void edge_scatter1() {
    int gw = (blockIdx.x * blockDim.x + threadIdx.x) >> 5;
    int lane = threadIdx.x & 31;
    int h = blockIdx.y;
    if (gw >= E_ALL) return;
    int d = g_dst[gw], s = g_src[gw], ra = g_rA[gw], rb = g_rB[gw];
    float dot = g_d1[h * N_NODES + d] + g_s1[h * N_NODES + s] + g_r1[h * N_RELS + ra];
    if (rb >= 0) dot += g_r1[h * N_RELS + rb];
    float lr = dot > 0.f ? dot : 0.2f * dot;
    float ev = __expf(-lr);
    const float* ps = g_projA + (size_t)s * 600 + h * 200 + 100;
    const float* rp = g_relproj1 + (h * N_RELS + ra) * NHID;
    const float* rpb = (rb >= 0) ? g_relproj1 + (h * N_RELS + rb) * NHID : nullptr;
    float* accrow = g_acc1 + ((size_t)h * N_NODES + d) * NHID;
    if (lane == 0) atomicAdd(&g_rowsum1[h * N_NODES + d], ev);
    #pragma unroll
    for (int t = 0; t < 4; t++) {
        int j = lane + 32 * t;
        if (j < NHID) {
            float v = ps[j] + rp[j];
            if (rpb) v += rpb[j];
            atomicAdd(&accrow[j], ev * v);
        }
    }
}

// ---------------- combine layer-1 -> x1 (elu) + layer-2 node scalars -------
__global__ void combine1() {
    int n = (blockIdx.x * blockDim.x + threadIdx.x) >> 5;
    int lane = threadIdx.x & 31;
    if (n >= N_NODES) return;
    float rs0 = g_rowsum1[n];
    float rs1 = g_rowsum1[N_NODES + n];
    bool h0 = rs0 != 0.f, h1 = rs1 != 0.f;
    float i0 = h0 ? 1.f / rs0 : 0.f;
    float i1 = h1 ? 1.f / rs1 : 0.f;
    const float* pd = g_projA + (size_t)n * 600;
    const float* a0 = g_acc1 + (size_t)n * NHID;
    const float* a1 = g_acc1 + ((size_t)N_NODES + n) * NHID;
    float* xr = g_x1 + (size_t)n * DIM;
    float d2 = 0.f, s2 = 0.f;
    #pragma unroll
    for (int t = 0; t < 4; t++) {
        int j = lane + 32 * t;
        if (j < NHID) {
            float hp0 = h0 ? pd[j] + a0[j] * i0 : 0.f;
            float hp1 = h1 ? pd[200 + j] + a1[j] * i1 : 0.f;
            float v0 = hp0 > 0.f ? hp0 : (__expf(hp0) - 1.f);
            float v1 = hp1 > 0.f ? hp1 : (__expf(hp1) - 1.f);
            xr[j] = v0;
            xr[100 + j] = v1;
            d2 += v0 * g_w2[j]       + v1 * g_w2[100 + j];
            s2 += v0 * g_w2[200 + j] + v1 * g_w2[300 + j];
        }
    }
    d2 = warp_sum(d2); s2 = warp_sum(s2);
    if (lane == 0) { g_d2[n] = d2; g_s2[n] = s2; }
}

// ---------------- edge scatter, layer 2 ----------------
__global__ void edge_scatter2() {
    int gw = (blockIdx.x * blockDim.x + threadIdx.x) >> 5;
    int lane = threadIdx.x & 31;
    if (gw >= E_ALL) return;
    int d = g_dst[gw], s = g_src[gw], ra = g_rA[gw], rb = g_rB[gw];
    float dot = g_d2[d] + g_s2[s] + g_r2[ra];
    if (rb >= 0) dot += g_r2[rb];
    float lr = dot > 0.f ? dot : 0.2f * dot;
    float ev = __expf(-lr);
    const float* ps = g_proj2 + (size_t)s * 400 + 200;
    const float* rp = g_relproj2 + ra * DIM;
    const float* rpb = (rb >= 0) ? g_relproj2 + rb * DIM : nullptr;
    float* accrow = g_acc2 + (size_t)d * DIM;
    if (lane == 0) atomicAdd(&g_rowsum2[d], ev);
    #pragma unroll
    for (int t = 0; t < 7; t++) {
        int j = lane + 32 * t;
        if (j < DIM) {
            float v = ps[j] + rp[j];
            if (rpb) v += rpb[j];
            atomicAdd(&accrow[j], ev * v);
        }
    }
}

// ---------------- finalize: out_ent = l2norm(entlin + mask*elu(hp)) --------
__global__ void finalize(float* __restrict__ out) {
    int n = (blockIdx.x * blockDim.x + threadIdx.x) >> 5;
    int lane = threadIdx.x & 31;
    if (n >= N_NODES) return;
    float rs = g_rowsum2[n];
    bool has = rs != 0.f;
    float iS = has ? 1.f / rs : 0.f;
    float mk = g_mask[n];
    const float* pd = g_proj2 + (size_t)n * 400;
    const float* lin = g_projA + (size_t)n * 600 + 400;
    const float* acc = g_acc2 + (size_t)n * DIM;
    float v[7];
    float ss = 0.f;
    #pragma unroll
    for (int t = 0; t < 7; t++) {
        int j = lane + 32 * t;
        float val = 0.f;
        if (j < DIM) {
            float hp = has ? pd[j] + acc[j] * iS : 0.f;
            float el = hp > 0.f ? hp : (expf(hp) - 1.f);
            val = lin[j] + mk * el;
            ss += val * val;
        }
        v[t] = val;
    }
    ss = warp_sum(ss);
    float sc = 1.f / fmaxf(sqrtf(ss), 1e-12f);
    #pragma unroll
    for (int t = 0; t < 7; t++) {
        int j = lane + 32 * t;
        if (j < DIM) out[(size_t)n * DIM + j] = v[t] * sc;
    }
}

__global__ void copy_tail(float* __restrict__ out) {
    int i = blockIdx.x * blockDim.x + threadIdx.x;
    const size_t base = (size_t)N_NODES * DIM;
    if (i < N_RELS * DIM) out[base + i] = g_outrel[i];
    if (i < N_NODES) out[base + N_RELS * DIM + i] = g_mask[i];
}

// ---------------- launch ----------------
extern "C" void kernel_launch(void* const* d_in, const int* in_sizes, int n_in,
                              void* d_out, int out_size) {
    const float* ent   = (const float*)d_in[0];
    const float* rel   = (const float*)d_in[1];
    const float* W_ent = (const float*)d_in[2];
    const float* W_gat = (const float*)d_in[3];
    const float* a_h   = (const float*)d_in[4];
    const float* a2_h  = (const float*)d_in[5];
    const float* a_o   = (const float*)d_in[6];
    const float* a2_o  = (const float*)d_in[7];
    const int*   batch = (const int*)d_in[8];
    const int*   elist = (const int*)d_in[9];
    const int*   etype = (const int*)d_in[10];
    const int*   nhop  = (const int*)d_in[11];
    float* out = (float*)d_out;
    int n_batch = in_sizes[8];

    zero_all<<<4096, 256>>>();
    prep<<<(E_ALL + 255) / 256, 256>>>(a_h, a_o, W_ent, elist, etype, nhop);
    mask_scatter<<<(n_batch + 255) / 256, 256>>>(batch, n_batch);
    fold_w<<<(NHEADS * 600 + 255) / 256, 256>>>(a_h, a2_h, a_o, a2_o);
    l2norm_scalars<<<(N_NODES * 32 + 255) / 256, 256>>>(ent);
    relproj1_k<<<(NHEADS * N_RELS * NHID + 255) / 256, 256>>>(rel, a_h);
    outrel_k<<<(N_RELS * DIM + 255) / 256, 256>>>(rel, W_gat);
    relproj2_k<<<(N_RELS * DIM + 255) / 256, 256>>>(a_o);
    rel_scalars<<<(NHEADS * N_RELS + 255) / 256, 256>>>(rel);

    {   // projA = [x@Bcat1^T | x@W_ent]  (N=600)
        dim3 grid((600 + BN - 1) / BN, (N_NODES + BM - 1) / BM);
        sgemm128<0><<<grid, 256>>>();
    }

    {
        dim3 grid((E_ALL + 7) / 8, NHEADS);
        edge_scatter1<<<grid, 256>>>();
    }
    combine1<<<(N_NODES * 32 + 255) / 256, 256>>>();

    {   // proj2 = x1 @ Bcat2^T  (N=400)
        dim3 grid((400 + BN - 1) / BN, (N_NODES + BM - 1) / BM);
        sgemm128<1><<<grid, 256>>>();
    }

    {
        dim3 grid((E_ALL + 7) / 8, 1);
        edge_scatter2<<<grid, 256>>>();
    }

    finalize<<<(N_NODES * 32 + 255) / 256, 256>>>(out);
    copy_tail<<<(N_RELS * DIM + 255) / 256, 256>>>(out);
}

// round 8
// speedup vs baseline: 1.4654x; 1.2008x over previous
#include <cuda_runtime.h>
#include <cuda_bf16.h>
#include <math.h>
#include <stdint.h>

#define N_NODES 50000
#define DIM     200
#define K_PAD   224
#define N_RELS  500
#define NHID    100
#define NHEADS  2
#define E_BASE  150000
#define E_NHOP  30000
#define E_ALL   180000

typedef __nv_bfloat16 bf16;

// ---------------- scratch (static device globals; no allocs) ----------------
__device__ __align__(16) bf16 g_xh[N_NODES * K_PAD];
__device__ __align__(16) bf16 g_xl[N_NODES * K_PAD];
__device__ __align__(16) bf16 g_x1h[N_NODES * K_PAD];
__device__ __align__(16) bf16 g_x1l[N_NODES * K_PAD];
__device__ __align__(16) bf16 g_BAh[600 * K_PAD];
__device__ __align__(16) bf16 g_BAl[600 * K_PAD];
__device__ __align__(16) bf16 g_B2h[400 * K_PAD];
__device__ __align__(16) bf16 g_B2l[400 * K_PAD];
__device__ float g_relproj1[NHEADS * N_RELS * NHID];
__device__ float g_projA[N_NODES * 600];        // cols 0-399: proj1, 400-599: entlin
__device__ int   g_dst[E_ALL];
__device__ int   g_src[E_ALL];
__device__ int   g_rA[E_ALL];
__device__ int   g_rB[E_ALL];
__device__ float g_rowsum1[NHEADS * N_NODES];
__device__ float g_acc1[NHEADS * N_NODES * NHID];
__device__ float g_outrel[N_RELS * DIM];
__device__ float g_relproj2[N_RELS * DIM];
__device__ float g_proj2[N_NODES * 400];
__device__ float g_rowsum2[N_NODES];
__device__ float g_acc2[N_NODES * DIM];
__device__ float g_mask[N_NODES];
// attention-scalar machinery
__device__ float g_w1[NHEADS * 600];
__device__ float g_w2[600];
__device__ float g_d1[NHEADS * N_NODES];
__device__ float g_s1[NHEADS * N_NODES];
__device__ float g_r1[NHEADS * N_RELS];
__device__ float g_d2[N_NODES];
__device__ float g_s2[N_NODES];
__device__ float g_r2[N_RELS];

// ---------------- helpers ----------------
__device__ __forceinline__ float warp_sum(float v) {
    #pragma unroll
    for (int o = 16; o; o >>= 1) v += __shfl_xor_sync(0xFFFFFFFFu, v, o);
    return v;
}

__device__ __forceinline__ void split_bf16(float x, bf16& hi, bf16& lo) {
    hi = __float2bfloat16_rn(x);
    lo = __float2bfloat16_rn(x - __bfloat162float(hi));
}

#define LDSM_X4(R, addr) asm volatile( \
    "ldmatrix.sync.aligned.m8n8.x4.shared.b16 {%0,%1,%2,%3}, [%4];" \
    : "=r"((R)[0]), "=r"((R)[1]), "=r"((R)[2]), "=r"((R)[3]) : "r"(addr))
#define LDSM_X2(R, addr) asm volatile( \
    "ldmatrix.sync.aligned.m8n8.x2.shared.b16 {%0,%1}, [%2];" \
    : "=r"((R)[0]), "=r"((R)[1]) : "r"(addr))
#define MMA_BF16(C, A, B) asm volatile( \
    "mma.sync.aligned.m16n8k16.row.col.f32.bf16.bf16.f32 " \
    "{%0,%1,%2,%3}, {%4,%5,%6,%7}, {%8,%9}, {%0,%1,%2,%3};" \
    : "+f"((C)[0]), "+f"((C)[1]), "+f"((C)[2]), "+f"((C)[3]) \
    : "r"((A)[0]), "r"((A)[1]), "r"((A)[2]), "r"((A)[3]), "r"((B)[0]), "r"((B)[1]))

// ---------------- folded attention vectors ----------------
__global__ void fold_w(const float* __restrict__ a_heads, const float* __restrict__ a2_h,
                       const float* __restrict__ a_out,   const float* __restrict__ a2_o) {
    int i = blockIdx.x * blockDim.x + threadIdx.x;
    if (i < NHEADS * 600) {
        int h = i / 600, k = i % 600;
        float s = 0.f;
        for (int j = 0; j < NHID; j++) s += a_heads[(h * NHID + j) * 600 + k] * a2_h[h * NHID + j];
        g_w1[i] = s;
    }
    if (i < 600) {
        float s = 0.f;
        for (int j = 0; j < 200; j++) s += a_out[j * 600 + i] * a2_o[j];
        g_w2[i] = s;
    }
}

// ---------------- prep: B-matrix bf16 splits + edge arrays ----------------
// NOTE: grid must cover max(600*K_PAD, E_ALL) threads!
__global__ void prep(const float* __restrict__ a_heads,
                     const float* __restrict__ a_out,
                     const float* __restrict__ W_ent,
                     const int* __restrict__ edge_list,
                     const int* __restrict__ edge_type,
                     const int* __restrict__ nhop) {
    int i = blockIdx.x * blockDim.x + threadIdx.x;
    if (i < 600 * K_PAD) {
        int j = i / K_PAD, k = i % K_PAD;
        float v = 0.f;
        if (k < DIM) {
            if (j < 400) {
                int h = j / 200, w = j % 200, sect = w / NHID, jr = w % NHID;
                v = a_heads[(h * NHID + jr) * 600 + sect * DIM + k];
            } else {
                v = W_ent[k * DIM + (j - 400)];
            }
        }
        bf16 hi, lo; split_bf16(v, hi, lo);
        g_BAh[i] = hi; g_BAl[i] = lo;
        if (i < 400 * K_PAD) {
            float v2 = 0.f;
            if (k < DIM) v2 = a_out[(j % 200) * 600 + (j / 200) * DIM + k];
            bf16 h2, l2; split_bf16(v2, h2, l2);
            g_B2h[i] = h2; g_B2l[i] = l2;
        }
    }
    if (i < E_ALL) {
        if (i < E_BASE) {
            g_dst[i] = edge_list[i];
            g_src[i] = edge_list[E_BASE + i];
            g_rA[i]  = edge_type[i];
            g_rB[i]  = -1;
        } else {
            int t = i - E_BASE;
            g_dst[i] = nhop[t * 4 + 3];
            g_src[i] = nhop[t * 4 + 0];
            g_rA[i]  = nhop[t * 4 + 1];
            g_rB[i]  = nhop[t * 4 + 2];
        }
    }
}

// ---------------- l2norm + bf16 split + layer-1 node scalars (fused) ------
__global__ void l2norm_conv(const float* __restrict__ in) {
    int n = (blockIdx.x * blockDim.x + threadIdx.x) >> 5;
    int lane = threadIdx.x & 31;
    if (n >= N_NODES) return;
    const float* r = in + (size_t)n * DIM;
    float v[7];
    float ss = 0.f;
    #pragma unroll
    for (int t = 0; t < 7; t++) {
        int j = lane + 32 * t;
        float x = (j < DIM) ? r[j] : 0.f;
        v[t] = x; ss += x * x;
    }
    ss = warp_sum(ss);
    float sc = 1.f / fmaxf(sqrtf(ss), 1e-12f);
    float a = 0.f, b = 0.f, c = 0.f, d = 0.f;
    bf16* xh = g_xh + (size_t)n * K_PAD;
    bf16* xl = g_xl + (size_t)n * K_PAD;
    #pragma unroll
    for (int t = 0; t < 7; t++) {
        int j = lane + 32 * t;
        if (j < K_PAD) {
            float xv = (j < DIM) ? v[t] * sc : 0.f;
            bf16 hi, lo; split_bf16(xv, hi, lo);
            xh[j] = hi; xl[j] = lo;
            if (j < DIM) {
                a += xv * g_w1[j];
                b += xv * g_w1[200 + j];
                c += xv * g_w1[600 + j];
                d += xv * g_w1[800 + j];
            }
        }
    }
    a = warp_sum(a); b = warp_sum(b); c = warp_sum(c); d = warp_sum(d);
    if (lane == 0) {
        g_d1[n] = a; g_s1[n] = b;
        g_d1[N_NODES + n] = c; g_s1[N_NODES + n] = d;
    }
}

// ---------------- zero accumulators ----------------
__global__ void zero_all() {
    int stride = gridDim.x * blockDim.x;
    for (int i = blockIdx.x * blockDim.x + threadIdx.x;
         i < NHEADS * N_NODES * NHID; i += stride) {
        g_acc1[i] = 0.f;
        if (i < N_NODES * DIM) g_acc2[i] = 0.f;
        if (i < NHEADS * N_NODES) g_rowsum1[i] = 0.f;
        if (i < N_NODES) { g_rowsum2[i] = 0.f; g_mask[i] = 0.f; }
    }
}

__global__ void mask_scatter(const int* __restrict__ batch, int n) {
    int i = blockIdx.x * blockDim.x + threadIdx.x;
    if (i < n) g_mask[batch[i]] = 1.0f;
}

// ---------------- relation projections (fp32, small) ----------------
__global__ void relproj1_k(const float* __restrict__ rel, const float* __restrict__ a_heads) {
    int i = blockIdx.x * blockDim.x + threadIdx.x;
    if (i >= NHEADS * N_RELS * NHID) return;
    int h = i / (N_RELS * NHID);
    int rem = i % (N_RELS * NHID);
    int r = rem / NHID, j = rem % NHID;
    const float* ar = a_heads + (h * NHID + j) * 600 + 400;
    const float* rr = rel + r * DIM;
    float s = 0.f;
    #pragma unroll 4
    for (int k = 0; k < DIM; k++) s += rr[k] * ar[k];
    g_relproj1[i] = s;
}

__global__ void outrel_k(const float* __restrict__ rel, const float* __restrict__ W_gat) {
    int i = blockIdx.x * blockDim.x + threadIdx.x;
    if (i >= N_RELS * DIM) return;
    int r = i / DIM, j = i % DIM;
    const float* rr = rel + r * DIM;
    float s = 0.f;
    #pragma unroll 4
    for (int k = 0; k < DIM; k++) s += rr[k] * W_gat[k * DIM + j];
    g_outrel[i] = s;
}

__global__ void relproj2_k(const float* __restrict__ a_out) {
    int i = blockIdx.x * blockDim.x + threadIdx.x;
    if (i >= N_RELS * DIM) return;
    int r = i / DIM, j = i % DIM;
    const float* rr = g_outrel + r * DIM;
    const float* ar = a_out + j * 600 + 400;
    float s = 0.f;
    #pragma unroll 4
    for (int k = 0; k < DIM; k++) s += rr[k] * ar[k];
    g_relproj2[i] = s;
}

__global__ void rel_scalars(const float* __restrict__ rel) {
    int i = blockIdx.x * blockDim.x + threadIdx.x;
    if (i < NHEADS * N_RELS) {
        int h = i / N_RELS, r = i % N_RELS;
        float s = 0.f;
        for (int k = 0; k < DIM; k++) s += rel[r * DIM + k] * g_w1[h * 600 + 400 + k];
        g_r1[i] = s;
    }
    if (i < N_RELS) {
        float s = 0.f;
        for (int k = 0; k < DIM; k++) s += g_outrel[i * DIM + k] * g_w2[400 + k];
        g_r2[i] = s;
    }
}

// ---------------- split-bf16 tensor GEMM: C[M,Nn] = A[M,K] @ B[Nn,K]^T ----
// 3-term split: Ahi*Bhi + Ahi*Blo + Alo*Bhi, fp32 accumulate. K padded to 224.
#define GBM 128
#define GBN 128
#define GBK 32
#define SROW 40   // smem row stride in bf16 (80B, 16B-aligned)

template <int SEL>
__global__ __launch_bounds__(256) void gemm_bf16s() {
    const bf16 *Ah, *Al, *Bh, *Bl; float* C; int M, Nn;
    if (SEL == 0) { Ah = g_xh;  Al = g_xl;  Bh = g_BAh; Bl = g_BAl; C = g_projA; M = N_NODES; Nn = 600; }
    else          { Ah = g_x1h; Al = g_x1l; Bh = g_B2h; Bl = g_B2l; C = g_proj2; M = N_NODES; Nn = 400; }

    __shared__ __align__(16) bf16 sAh[GBM * SROW];
    __shared__ __align__(16) bf16 sAl[GBM * SROW];
    __shared__ __align__(16) bf16 sBh[GBN * SROW];
    __shared__ __align__(16) bf16 sBl[GBN * SROW];

    int tid = threadIdx.x;
    int lane = tid & 31;
    int w = tid >> 5;
    int wm = (w & 3) * 32;      // 4 warps along M
    int wn = (w >> 2) * 64;     // 2 warps along N
    int row0 = blockIdx.y * GBM;
    int col0 = blockIdx.x * GBN;

    uint32_t uAh = (uint32_t)__cvta_generic_to_shared(sAh);
    uint32_t uAl = (uint32_t)__cvta_generic_to_shared(sAl);
    uint32_t uBh = (uint32_t)__cvta_generic_to_shared(sBh);
    uint32_t uBl = (uint32_t)__cvta_generic_to_shared(sBl);

    float acc[2][8][4];
    #pragma unroll
    for (int mt = 0; mt < 2; mt++)
        #pragma unroll
        for (int nt = 0; nt < 8; nt++)
            #pragma unroll
            for (int q = 0; q < 4; q++) acc[mt][nt][q] = 0.f;

    for (int k0 = 0; k0 < K_PAD; k0 += GBK) {
        #pragma unroll
        for (int i = 0; i < 2; i++) {
            int idx = tid + 256 * i;
            int r = idx >> 2, c4 = idx & 3;
            uint4 zero = make_uint4(0, 0, 0, 0);
            bool aok = (row0 + r) < M;
            bool bok = (col0 + r) < Nn;
            uint4 va = aok ? *(const uint4*)(Ah + (size_t)(row0 + r) * K_PAD + k0 + c4 * 8) : zero;
            uint4 vb = aok ? *(const uint4*)(Al + (size_t)(row0 + r) * K_PAD + k0 + c4 * 8) : zero;
            uint4 vc = bok ? *(const uint4*)(Bh + (size_t)(col0 + r) * K_PAD + k0 + c4 * 8) : zero;
            uint4 vd = bok ? *(const uint4*)(Bl + (size_t)(col0 + r) * K_PAD + k0 + c4 * 8) : zero;
            *(uint4*)(sAh + r * SROW + c4 * 8) = va;
            *(uint4*)(sAl + r * SROW + c4 * 8) = vb;
            *(uint4*)(sBh + r * SROW + c4 * 8) = vc;
            *(uint4*)(sBl + r * SROW + c4 * 8) = vd;
        }
        __syncthreads();

        #pragma unroll
        for (int k16 = 0; k16 < GBK; k16 += 16) {
            uint32_t ah[2][4], al[2][4];
            #pragma unroll
            for (int mt = 0; mt < 2; mt++) {
                uint32_t off = (uint32_t)((wm + mt * 16 + (lane & 15)) * SROW + k16 + (lane >> 4) * 8) * 2;
                LDSM_X4(ah[mt], uAh + off);
                LDSM_X4(al[mt], uAl + off);
            }
            #pragma unroll
            for (int nt = 0; nt < 8; nt++) {
                uint32_t boff = (uint32_t)((wn + nt * 8 + (lane & 7)) * SROW + k16 + ((lane >> 3) & 1) * 8) * 2;
                uint32_t bh[2], bl[2];
                LDSM_X2(bh, uBh + boff);
                LDSM_X2(bl, uBl + boff);
                #pragma unroll
                for (int mt = 0; mt < 2; mt++) {
                    MMA_BF16(acc[mt][nt], ah[mt], bh);
                    MMA_BF16(acc[mt][nt], ah[mt], bl);
                    MMA_BF16(acc[mt][nt], al[mt], bh);
                }
            }
        }
        __syncthreads();
    }

    #pragma unroll
    for (int mt = 0; mt < 2; mt++) {
        int r0 = row0 + wm + mt * 16 + (lane >> 2);
        #pragma unroll
        for (int nt = 0; nt < 8; nt++) {
            int c = col0 + wn + nt * 8 + (lane & 3) * 2;
            if (c < Nn) {
                if (r0 < M)
                    *(float2*)(C + (size_t)r0 * Nn + c) = make_float2(acc[mt][nt][0], acc[mt][nt][1]);
                if (r0 + 8 < M)
                    *(float2*)(C + (size_t)(r0 + 8) * Nn + c) = make_float2(acc[mt][nt][2], acc[mt][nt][3]);
            }
        }
    }
}

// ---------------- edge scatter, layer 1 (warp per edge, head = blockIdx.y) --
__global__ void edge_scatter1() {
    int gw = (blockIdx.x * blockDim.x + threadIdx.x) >> 5;
    int lane = threadIdx.x & 31;
    int h = blockIdx.y;
    if (gw >= E_ALL) return;
    int d = g_dst[gw], s = g_src[gw], ra = g_rA[gw], rb = g_rB[gw];
    float dot = g_d1[h * N_NODES + d] + g_s1[h * N_NODES + s] + g_r1[h * N_RELS + ra];
    if (rb >= 0) dot += g_r1[h * N_RELS + rb];
    float lr = dot > 0.f ? dot : 0.2f * dot;
    float ev = __expf(-lr);
    const float* ps = g_projA + (size_t)s * 600 + h * 200 + 100;
    const float* rp = g_relproj1 + (h * N_RELS + ra) * NHID;
    const float* rpb = (rb >= 0) ? g_relproj1 + (h * N_RELS + rb) * NHID : nullptr;
    float* accrow = g_acc1 + ((size_t)h * N_NODES + d) * NHID;
    if (lane == 0) atomicAdd(&g_rowsum1[h * N_NODES + d], ev);
    #pragma unroll
    for (int t = 0; t < 4; t++) {
        int j = lane + 32 * t;
        if (j < NHID) {
            float v = ps[j] + rp[j];
            if (rpb) v += rpb[j];
            atomicAdd(&accrow[j], ev * v);
        }
    }
}

// ---------------- combine layer-1 -> x1 split + layer-2 node scalars -------
__global__ void combine1() {
    int n = (blockIdx.x * blockDim.x + threadIdx.x) >> 5;
    int lane = threadIdx.x & 31;
    if (n >= N_NODES) return;
    float rs0 = g_rowsum1[n];
    float rs1 = g_rowsum1[N_NODES + n];
    bool h0 = rs0 != 0.f, h1 = rs1 != 0.f;
    float i0 = h0 ? 1.f / rs0 : 0.f;
    float i1 = h1 ? 1.f / rs1 : 0.f;
    const float* pd = g_projA + (size_t)n * 600;
    const float* a0 = g_acc1 + (size_t)n * NHID;
    const float* a1 = g_acc1 + ((size_t)N_NODES + n) * NHID;
    bf16* xh = g_x1h + (size_t)n * K_PAD;
    bf16* xl = g_x1l + (size_t)n * K_PAD;
    float d2 = 0.f, s2 = 0.f;
    #pragma unroll
    for (int t = 0; t < 4; t++) {
        int j = lane + 32 * t;
        if (j < NHID) {
            float hp0 = h0 ? pd[j] + a0[j] * i0 : 0.f;
            float hp1 = h1 ? pd[200 + j] + a1[j] * i1 : 0.f;
            float v0 = hp0 > 0.f ? hp0 : (__expf(hp0) - 1.f);
            float v1 = hp1 > 0.f ? hp1 : (__expf(hp1) - 1.f);
            bf16 hh, ll;
            split_bf16(v0, hh, ll); xh[j] = hh; xl[j] = ll;
            split_bf16(v1, hh, ll); xh[100 + j] = hh; xl[100 + j] = ll;
            d2 += v0 * g_w2[j]       + v1 * g_w2[100 + j];
            s2 += v0 * g_w2[200 + j] + v1 * g_w2[300 + j];
        }
    }
    int jp = 200 + lane;
    if (jp < K_PAD) { xh[jp] = __float2bfloat16_rn(0.f); xl[jp] = __float2bfloat16_rn(0.f); }
    d2 = warp_sum(d2); s2 = warp_sum(s2);
    if (lane == 0) { g_d2[n] = d2; g_s2[n] = s2; }
}

// ---------------- edge scatter, layer 2 ----------------
__global__ void edge_scatter2() {
    int gw = (blockIdx.x * blockDim.x + threadIdx.x) >> 5;
    int lane = threadIdx.x & 31;
    if (gw >= E_ALL) return;
    int d = g_dst[gw], s = g_src[gw], ra = g_rA[gw], rb = g_rB[gw];
    float dot = g_d2[d] + g_s2[s] + g_r2[ra];
    if (rb >= 0) dot += g_r2[rb];
    float lr = dot > 0.f ? dot : 0.2f * dot;
    float ev = __expf(-lr);
    const float* ps = g_proj2 + (size_t)s * 400 + 200;
    const float* rp = g_relproj2 + ra * DIM;
    const float* rpb = (rb >= 0) ? g_relproj2 + rb * DIM : nullptr;
    float* accrow = g_acc2 + (size_t)d * DIM;
    if (lane == 0) atomicAdd(&g_rowsum2[d], ev);
    #pragma unroll
    for (int t = 0; t < 7; t++) {
        int j = lane + 32 * t;
        if (j < DIM) {
            float v = ps[j] + rp[j];
            if (rpb) v += rpb[j];
            atomicAdd(&accrow[j], ev * v);
        }
    }
}

// ---------------- finalize: out_ent = l2norm(entlin + mask*elu(hp)) --------
__global__ void finalize(float* __restrict__ out) {
    int n = (blockIdx.x * blockDim.x + threadIdx.x) >> 5;
    int lane = threadIdx.x & 31;
    if (n >= N_NODES) return;
    float rs = g_rowsum2[n];
    bool has = rs != 0.f;
    float iS = has ? 1.f / rs : 0.f;
    float mk = g_mask[n];
    const float* pd = g_proj2 + (size_t)n * 400;
    const float* lin = g_projA + (size_t)n * 600 + 400;
    const float* acc = g_acc2 + (size_t)n * DIM;
    float v[7];
    float ss = 0.f;
    #pragma unroll
    for (int t = 0; t < 7; t++) {
        int j = lane + 32 * t;
        float val = 0.f;
        if (j < DIM) {
            float hp = has ? pd[j] + acc[j] * iS : 0.f;
            float el = hp > 0.f ? hp : (expf(hp) - 1.f);
            val = lin[j] + mk * el;
            ss += val * val;
        }
        v[t] = val;
    }
    ss = warp_sum(ss);
    float sc = 1.f / fmaxf(sqrtf(ss), 1e-12f);
    #pragma unroll
    for (int t = 0; t < 7; t++) {
        int j = lane + 32 * t;
        if (j < DIM) out[(size_t)n * DIM + j] = v[t] * sc;
    }
}

__global__ void copy_tail(float* __restrict__ out) {
    int i = blockIdx.x * blockDim.x + threadIdx.x;
    const size_t base = (size_t)N_NODES * DIM;
    if (i < N_RELS * DIM) out[base + i] = g_outrel[i];
    if (i < N_NODES) out[base + N_RELS * DIM + i] = g_mask[i];
}

// ---------------- launch ----------------
extern "C" void kernel_launch(void* const* d_in, const int* in_sizes, int n_in,
                              void* d_out, int out_size) {
    const float* ent   = (const float*)d_in[0];
    const float* rel   = (const float*)d_in[1];
    const float* W_ent = (const float*)d_in[2];
    const float* W_gat = (const float*)d_in[3];
    const float* a_h   = (const float*)d_in[4];
    const float* a2_h  = (const float*)d_in[5];
    const float* a_o   = (const float*)d_in[6];
    const float* a2_o  = (const float*)d_in[7];
    const int*   batch = (const int*)d_in[8];
    const int*   elist = (const int*)d_in[9];
    const int*   etype = (const int*)d_in[10];
    const int*   nhop  = (const int*)d_in[11];
    float* out = (float*)d_out;
    int n_batch = in_sizes[8];

    const int PREP_N = (600 * K_PAD > E_ALL) ? 600 * K_PAD : E_ALL;  // cover BOTH workloads

    fold_w<<<(NHEADS * 600 + 255) / 256, 256>>>(a_h, a2_h, a_o, a2_o);          // 0
    prep<<<(PREP_N + 255) / 256, 256>>>(a_h, a_o, W_ent, elist, etype, nhop);   // 1
    l2norm_conv<<<(N_NODES * 32 + 255) / 256, 256>>>(ent);                      // 2

    {   // 3 — projA = [x@Bcat1^T | x@W_ent]  (profiled launch slot)
        dim3 grid((600 + GBN - 1) / GBN, (N_NODES + GBM - 1) / GBM);
        gemm_bf16s<0><<<grid, 256>>>();
    }

    zero_all<<<4096, 256>>>();                                                  // 4
    mask_scatter<<<(n_batch + 255) / 256, 256>>>(batch, n_batch);               // 5
    relproj1_k<<<(NHEADS * N_RELS * NHID + 255) / 256, 256>>>(rel, a_h);        // 6
    outrel_k<<<(N_RELS * DIM + 255) / 256, 256>>>(rel, W_gat);                  // 7
    relproj2_k<<<(N_RELS * DIM + 255) / 256, 256>>>(a_o);                       // 8
    rel_scalars<<<(NHEADS * N_RELS + 255) / 256, 256>>>(rel);                   // 9

    {
        dim3 grid((E_ALL + 7) / 8, NHEADS);
        edge_scatter1<<<grid, 256>>>();                                         // 10
    }
    combine1<<<(N_NODES * 32 + 255) / 256, 256>>>();                            // 11

    {   // proj2 = x1 @ Bcat2^T
        dim3 grid((400 + GBN - 1) / GBN, (N_NODES + GBM - 1) / GBM);
        gemm_bf16s<1><<<grid, 256>>>();                                         // 12
    }

    {
        dim3 grid((E_ALL + 7) / 8, 1);
        edge_scatter2<<<grid, 256>>>();                                         // 13
    }

    finalize<<<(N_NODES * 32 + 255) / 256, 256>>>(out);                         // 14
    copy_tail<<<(N_RELS * DIM + 255) / 256, 256>>>(out);                        // 15
}

// round 9
// speedup vs baseline: 1.8799x; 1.2829x over previous
#include <cuda_runtime.h>
#include <cuda_bf16.h>
#include <math.h>
#include <stdint.h>

#define N_NODES 50000
#define DIM     200
#define K_PAD   224
#define N_RELS  500
#define NHID    100
#define NHEADS  2
#define E_BASE  150000
#define E_NHOP  30000
#define E_ALL   180000

typedef __nv_bfloat16 bf16;

// ---------------- scratch (static device globals; no allocs) ----------------
__device__ __align__(16) bf16 g_xh[N_NODES * K_PAD];
__device__ __align__(16) bf16 g_xl[N_NODES * K_PAD];
__device__ __align__(16) bf16 g_x1h[N_NODES * K_PAD];
__device__ __align__(16) bf16 g_x1l[N_NODES * K_PAD];
__device__ __align__(16) bf16 g_BAh[600 * K_PAD];
__device__ __align__(16) bf16 g_BAl[600 * K_PAD];
__device__ __align__(16) bf16 g_B2h[400 * K_PAD];
__device__ __align__(16) bf16 g_B2l[400 * K_PAD];
__device__ float g_relproj1[NHEADS * N_RELS * NHID];
__device__ float g_projA[N_NODES * 600];        // cols 0-399: proj1, 400-599: entlin
__device__ int   g_dst[E_ALL];
__device__ int   g_src[E_ALL];
__device__ int   g_rA[E_ALL];
__device__ int   g_rB[E_ALL];
__device__ float g_rowsum1[NHEADS * N_NODES];
__device__ float g_acc1[NHEADS * N_NODES * NHID];
__device__ float g_outrel[N_RELS * DIM];
__device__ float g_relproj2[N_RELS * DIM];
__device__ float g_proj2[N_NODES * 400];
__device__ float g_rowsum2[N_NODES];
__device__ float g_acc2[N_NODES * DIM];
__device__ float g_mask[N_NODES];
// attention-scalar machinery
__device__ float g_w1[NHEADS * 600];
__device__ float g_w2[600];
__device__ float g_d1[NHEADS * N_NODES];
__device__ float g_s1[NHEADS * N_NODES];
__device__ float g_r1[NHEADS * N_RELS];
__device__ float g_d2[N_NODES];
__device__ float g_s2[N_NODES];
__device__ float g_r2[N_RELS];

// ---------------- helpers ----------------
__device__ __forceinline__ float warp_sum(float v) {
    #pragma unroll
    for (int o = 16; o; o >>= 1) v += __shfl_xor_sync(0xFFFFFFFFu, v, o);
    return v;
}

__device__ __forceinline__ void split_bf16(float x, bf16& hi, bf16& lo) {
    hi = __float2bfloat16_rn(x);
    lo = __float2bfloat16_rn(x - __bfloat162float(hi));
}

#define LDSM_X4(R, addr) asm volatile( \
    "ldmatrix.sync.aligned.m8n8.x4.shared.b16 {%0,%1,%2,%3}, [%4];" \
    : "=r"((R)[0]), "=r"((R)[1]), "=r"((R)[2]), "=r"((R)[3]) : "r"(addr))
#define LDSM_X2(R, addr) asm volatile( \
    "ldmatrix.sync.aligned.m8n8.x2.shared.b16 {%0,%1}, [%2];" \
    : "=r"((R)[0]), "=r"((R)[1]) : "r"(addr))
#define MMA_BF16(C, A, B) asm volatile( \
    "mma.sync.aligned.m16n8k16.row.col.f32.bf16.bf16.f32 " \
    "{%0,%1,%2,%3}, {%4,%5,%6,%7}, {%8,%9}, {%0,%1,%2,%3};" \
    : "+f"((C)[0]), "+f"((C)[1]), "+f"((C)[2]), "+f"((C)[3]) \
    : "r"((A)[0]), "r"((A)[1]), "r"((A)[2]), "r"((A)[3]), "r"((B)[0]), "r"((B)[1]))

__device__ __forceinline__ void cp_async16(uint32_t dst, const void* src, int szbytes) {
    asm volatile("cp.async.cg.shared.global [%0], [%1], 16, %2;"
                 :: "r"(dst), "l"(src), "r"(szbytes));
}
#define CP_COMMIT() asm volatile("cp.async.commit_group;")
#define CP_WAIT(N)  asm volatile("cp.async.wait_group %0;" :: "n"(N))

// ---------------- folded attention vectors ----------------
__global__ void fold_w(const float* __restrict__ a_heads, const float* __restrict__ a2_h,
                       const float* __restrict__ a_out,   const float* __restrict__ a2_o) {
    int i = blockIdx.x * blockDim.x + threadIdx.x;
    if (i < NHEADS * 600) {
        int h = i / 600, k = i % 600;
        float s = 0.f;
        for (int j = 0; j < NHID; j++) s += a_heads[(h * NHID + j) * 600 + k] * a2_h[h * NHID + j];
        g_w1[i] = s;
    }
    if (i < 600) {
        float s = 0.f;
        for (int j = 0; j < 200; j++) s += a_out[j * 600 + i] * a2_o[j];
        g_w2[i] = s;
    }
}

// ---------------- prep: B-matrix bf16 splits + edge arrays ----------------
// grid must cover max(600*K_PAD, E_ALL) threads
__global__ void prep(const float* __restrict__ a_heads,
                     const float* __restrict__ a_out,
                     const float* __restrict__ W_ent,
                     const int* __restrict__ edge_list,
                     const int* __restrict__ edge_type,
                     const int* __restrict__ nhop) {
    int i = blockIdx.x * blockDim.x + threadIdx.x;
    if (i < 600 * K_PAD) {
        int j = i / K_PAD, k = i % K_PAD;
        float v = 0.f;
        if (k < DIM) {
            if (j < 400) {
                int h = j / 200, w = j % 200, sect = w / NHID, jr = w % NHID;
                v = a_heads[(h * NHID + jr) * 600 + sect * DIM + k];
            } else {
                v = W_ent[k * DIM + (j - 400)];
            }
        }
        bf16 hi, lo; split_bf16(v, hi, lo);
        g_BAh[i] = hi; g_BAl[i] = lo;
        if (i < 400 * K_PAD) {
            float v2 = 0.f;
            if (k < DIM) v2 = a_out[(j % 200) * 600 + (j / 200) * DIM + k];
            bf16 h2, l2; split_bf16(v2, h2, l2);
            g_B2h[i] = h2; g_B2l[i] = l2;
        }
    }
    if (i < E_ALL) {
        if (i < E_BASE) {
            g_dst[i] = edge_list[i];
            g_src[i] = edge_list[E_BASE + i];
            g_rA[i]  = edge_type[i];
            g_rB[i]  = -1;
        } else {
            int t = i - E_BASE;
            g_dst[i] = nhop[t * 4 + 3];
            g_src[i] = nhop[t * 4 + 0];
            g_rA[i]  = nhop[t * 4 + 1];
            g_rB[i]  = nhop[t * 4 + 2];
        }
    }
}

// ---------------- l2norm + bf16 split + layer-1 node scalars (fused) ------
__global__ void l2norm_conv(const float* __restrict__ in) {
    int n = (blockIdx.x * blockDim.x + threadIdx.x) >> 5;
    int lane = threadIdx.x & 31;
    if (n >= N_NODES) return;
    const float* r = in + (size_t)n * DIM;
    float v[7];
    float ss = 0.f;
    #pragma unroll
    for (int t = 0; t < 7; t++) {
        int j = lane + 32 * t;
        float x = (j < DIM) ? r[j] : 0.f;
        v[t] = x; ss += x * x;
    }
    ss = warp_sum(ss);
    float sc = 1.f / fmaxf(sqrtf(ss), 1e-12f);
    float a = 0.f, b = 0.f, c = 0.f, d = 0.f;
    bf16* xh = g_xh + (size_t)n * K_PAD;
    bf16* xl = g_xl + (size_t)n * K_PAD;
    #pragma unroll
    for (int t = 0; t < 7; t++) {
        int j = lane + 32 * t;
        if (j < K_PAD) {
            float xv = (j < DIM) ? v[t] * sc : 0.f;
            bf16 hi, lo; split_bf16(xv, hi, lo);
            xh[j] = hi; xl[j] = lo;
            if (j < DIM) {
                a += xv * g_w1[j];
                b += xv * g_w1[200 + j];
                c += xv * g_w1[600 + j];
                d += xv * g_w1[800 + j];
            }
        }
    }
    a = warp_sum(a); b = warp_sum(b); c = warp_sum(c); d = warp_sum(d);
    if (lane == 0) {
        g_d1[n] = a; g_s1[n] = b;
        g_d1[N_NODES + n] = c; g_s1[N_NODES + n] = d;
    }
}

// ---------------- zero accumulators ----------------
__global__ void zero_all() {
    int stride = gridDim.x * blockDim.x;
    for (int i = blockIdx.x * blockDim.x + threadIdx.x;
         i < NHEADS * N_NODES * NHID; i += stride) {
        g_acc1[i] = 0.f;
        if (i < N_NODES * DIM) g_acc2[i] = 0.f;
        if (i < NHEADS * N_NODES) g_rowsum1[i] = 0.f;
        if (i < N_NODES) { g_rowsum2[i] = 0.f; g_mask[i] = 0.f; }
    }
}

__global__ void mask_scatter(const int* __restrict__ batch, int n) {
    int i = blockIdx.x * blockDim.x + threadIdx.x;
    if (i < n) g_mask[batch[i]] = 1.0f;
}

// ---------------- relation projections (fp32, small) ----------------
__global__ void relproj1_k(const float* __restrict__ rel, const float* __restrict__ a_heads) {
    int i = blockIdx.x * blockDim.x + threadIdx.x;
    if (i >= NHEADS * N_RELS * NHID) return;
    int h = i / (N_RELS * NHID);
    int rem = i % (N_RELS * NHID);
    int r = rem / NHID, j = rem % NHID;
    const float* ar = a_heads + (h * NHID + j) * 600 + 400;
    const float* rr = rel + r * DIM;
    float s = 0.f;
    #pragma unroll 4
    for (int k = 0; k < DIM; k++) s += rr[k] * ar[k];
    g_relproj1[i] = s;
}

__global__ void outrel_k(const float* __restrict__ rel, const float* __restrict__ W_gat) {
    int i = blockIdx.x * blockDim.x + threadIdx.x;
    if (i >= N_RELS * DIM) return;
    int r = i / DIM, j = i % DIM;
    const float* rr = rel + r * DIM;
    float s = 0.f;
    #pragma unroll 4
    for (int k = 0; k < DIM; k++) s += rr[k] * W_gat[k * DIM + j];
    g_outrel[i] = s;
}

__global__ void relproj2_k(const float* __restrict__ a_out) {
    int i = blockIdx.x * blockDim.x + threadIdx.x;
    if (i >= N_RELS * DIM) return;
    int r = i / DIM, j = i % DIM;
    const float* rr = g_outrel + r * DIM;
    const float* ar = a_out + j * 600 + 400;
    float s = 0.f;
    #pragma unroll 4
    for (int k = 0; k < DIM; k++) s += rr[k] * ar[k];
    g_relproj2[i] = s;
}

__global__ void rel_scalars(const float* __restrict__ rel) {
    int i = blockIdx.x * blockDim.x + threadIdx.x;
    if (i < NHEADS * N_RELS) {
        int h = i / N_RELS, r = i % N_RELS;
        float s = 0.f;
        for (int k = 0; k < DIM; k++) s += rel[r * DIM + k] * g_w1[h * 600 + 400 + k];
        g_r1[i] = s;
    }
    if (i < N_RELS) {
        float s = 0.f;
        for (int k = 0; k < DIM; k++) s += g_outrel[i * DIM + k] * g_w2[400 + k];
        g_r2[i] = s;
    }
}

// ---------------- split-bf16 tensor GEMM with cp.async double buffering ----
#define GBM 128
#define GBN 128
#define GBK 32
#define SROW 40
#define TILE (GBM * SROW)            // bf16 elems per array per stage
#define STAGE_ELEMS (4 * TILE)
#define SMEM_BYTES (2 * STAGE_ELEMS * 2)
#define NKCH (K_PAD / GBK)           // 7

extern __shared__ bf16 smem_dyn[];

template <int SEL>
__global__ __launch_bounds__(256, 2) void gemm_bf16s() {
    const bf16 *Ah, *Al, *Bh, *Bl; float* C; int M, Nn;
    if (SEL == 0) { Ah = g_xh;  Al = g_xl;  Bh = g_BAh; Bl = g_BAl; C = g_projA; M = N_NODES; Nn = 600; }
    else          { Ah = g_x1h; Al = g_x1l; Bh = g_B2h; Bl = g_B2l; C = g_proj2; M = N_NODES; Nn = 400; }

    int tid = threadIdx.x;
    int lane = tid & 31;
    int w = tid >> 5;
    int wm = (w & 3) * 32;      // 4 warps along M
    int wn = (w >> 2) * 64;     // 2 warps along N
    int row0 = blockIdx.y * GBM;
    int col0 = blockIdx.x * GBN;

    uint32_t ubase = (uint32_t)__cvta_generic_to_shared(smem_dyn);

    // per-thread load slots: 2 chunks per array, 4 arrays
    int r_ld[2], c8_ld[2];
    #pragma unroll
    for (int i = 0; i < 2; i++) { int idx = tid + 256 * i; r_ld[i] = idx >> 2; c8_ld[i] = (idx & 3) * 8; }
    bool aok[2], bok[2];
    #pragma unroll
    for (int i = 0; i < 2; i++) { aok[i] = (row0 + r_ld[i]) < M; bok[i] = (col0 + r_ld[i]) < Nn; }

    float acc[2][8][4];
    #pragma unroll
    for (int mt = 0; mt < 2; mt++)
        #pragma unroll
        for (int nt = 0; nt < 8; nt++)
            #pragma unroll
            for (int q = 0; q < 4; q++) acc[mt][nt][q] = 0.f;

    auto load_stage = [&](int s, int k0) {
        uint32_t sb = ubase + (uint32_t)(s * STAGE_ELEMS) * 2;
        #pragma unroll
        for (int i = 0; i < 2; i++) {
            int r = r_ld[i], c8 = c8_ld[i];
            uint32_t doff = (uint32_t)(r * SROW + c8) * 2;
            size_t arow = (size_t)(row0 + r) * K_PAD + k0 + c8;
            size_t brow = (size_t)(col0 + r) * K_PAD + k0 + c8;
            cp_async16(sb + 0 * TILE * 2 + doff, Ah + arow, aok[i] ? 16 : 0);
            cp_async16(sb + 1 * TILE * 2 + doff, Al + arow, aok[i] ? 16 : 0);
            cp_async16(sb + 2 * TILE * 2 + doff, Bh + brow, bok[i] ? 16 : 0);
            cp_async16(sb + 3 * TILE * 2 + doff, Bl + brow, bok[i] ? 16 : 0);
        }
        CP_COMMIT();
    };

    load_stage(0, 0);

    for (int kt = 0; kt < NKCH; kt++) {
        if (kt + 1 < NKCH) load_stage((kt + 1) & 1, (kt + 1) * GBK);
        if (kt + 1 < NKCH) { CP_WAIT(1); } else { CP_WAIT(0); }
        __syncthreads();

        uint32_t sb = ubase + (uint32_t)((kt & 1) * STAGE_ELEMS) * 2;
        uint32_t uAh = sb;
        uint32_t uAl = sb + TILE * 2;
        uint32_t uBh = sb + 2 * TILE * 2;
        uint32_t uBl = sb + 3 * TILE * 2;

        #pragma unroll
        for (int k16 = 0; k16 < GBK; k16 += 16) {
            uint32_t ah[2][4], al[2][4];
            #pragma unroll
            for (int mt = 0; mt < 2; mt++) {
                uint32_t off = (uint32_t)((wm + mt * 16 + (lane & 15)) * SROW + k16 + (lane >> 4) * 8) * 2;
                LDSM_X4(ah[mt], uAh + off);
                LDSM_X4(al[mt], uAl + off);
            }
            #pragma unroll
            for (int nt = 0; nt < 8; nt++) {
                uint32_t boff = (uint32_t)((wn + nt * 8 + (lane & 7)) * SROW + k16 + ((lane >> 3) & 1) * 8) * 2;
                uint32_t bh[2], bl[2];
                LDSM_X2(bh, uBh + boff);
                LDSM_X2(bl, uBl + boff);
                #pragma unroll
                for (int mt = 0; mt < 2; mt++) {
                    MMA_BF16(acc[mt][nt], ah[mt], bh);
                    MMA_BF16(acc[mt][nt], ah[mt], bl);
                    MMA_BF16(acc[mt][nt], al[mt], bh);
                }
            }
        }
        __syncthreads();
    }

    #pragma unroll
    for (int mt = 0; mt < 2; mt++) {
        int r0 = row0 + wm + mt * 16 + (lane >> 2);
        #pragma unroll
        for (int nt = 0; nt < 8; nt++) {
            int c = col0 + wn + nt * 8 + (lane & 3) * 2;
            if (c < Nn) {
                if (r0 < M)
                    *(float2*)(C + (size_t)r0 * Nn + c) = make_float2(acc[mt][nt][0], acc[mt][nt][1]);
                if (r0 + 8 < M)
                    *(float2*)(C + (size_t)(r0 + 8) * Nn + c) = make_float2(acc[mt][nt][2], acc[mt][nt][3]);
            }
        }
    }
}

// ---------------- edge scatter, layer 1 (warp per edge, both heads) -------
__global__ void edge_scatter1() {
    int gw = (blockIdx.x * blockDim.x + threadIdx.x) >> 5;
    int lane = threadIdx.x & 31;
    if (gw >= E_ALL) return;
    int d = g_dst[gw], s = g_src[gw], ra = g_rA[gw], rb = g_rB[gw];
    float dot0 = g_d1[d] + g_s1[s] + g_r1[ra];
    float dot1 = g_d1[N_NODES + d] + g_s1[N_NODES + s] + g_r1[N_RELS + ra];
    if (rb >= 0) { dot0 += g_r1[rb]; dot1 += g_r1[N_RELS + rb]; }
    float lr0 = dot0 > 0.f ? dot0 : 0.2f * dot0;
    float lr1 = dot1 > 0.f ? dot1 : 0.2f * dot1;
    float ev0 = __expf(-lr0);
    float ev1 = __expf(-lr1);
    const float* ps = g_projA + (size_t)s * 600;
    const float* rp0 = g_relproj1 + ra * NHID;
    const float* rp1 = g_relproj1 + (N_RELS + ra) * NHID;
    const float* rp0b = (rb >= 0) ? g_relproj1 + rb * NHID : nullptr;
    const float* rp1b = (rb >= 0) ? g_relproj1 + (N_RELS + rb) * NHID : nullptr;
    float* acc0 = g_acc1 + (size_t)d * NHID;
    float* acc1 = g_acc1 + ((size_t)N_NODES + d) * NHID;
    if (lane == 0) {
        atomicAdd(&g_rowsum1[d], ev0);
        atomicAdd(&g_rowsum1[N_NODES + d], ev1);
    }
    #pragma unroll
    for (int t = 0; t < 4; t++) {
        int j = lane + 32 * t;
        if (j < NHID) {
            float v0 = ps[100 + j] + rp0[j];
            float v1 = ps[300 + j] + rp1[j];
            if (rb >= 0) { v0 += rp0b[j]; v1 += rp1b[j]; }
            atomicAdd(&acc0[j], ev0 * v0);
            atomicAdd(&acc1[j], ev1 * v1);
        }
    }
}

// ---------------- combine layer-1 -> x1 split + layer-2 node scalars -------
__global__ void combine1() {
    int n = (blockIdx.x * blockDim.x + threadIdx.x) >> 5;
    int lane = threadIdx.x & 31;
    if (n >= N_NODES) return;
    float rs0 = g_rowsum1[n];
    float rs1 = g_rowsum1[N_NODES + n];
    bool h0 = rs0 != 0.f, h1 = rs1 != 0.f;
    float i0 = h0 ? 1.f / rs0 : 0.f;
    float i1 = h1 ? 1.f / rs1 : 0.f;
    const float* pd = g_projA + (size_t)n * 600;
    const float* a0 = g_acc1 + (size_t)n * NHID;
    const float* a1 = g_acc1 + ((size_t)N_NODES + n) * NHID;
    bf16* xh = g_x1h + (size_t)n * K_PAD;
    bf16* xl = g_x1l + (size_t)n * K_PAD;
    float d2 = 0.f, s2 = 0.f;
    #pragma unroll
    for (int t = 0; t < 4; t++) {
        int j = lane + 32 * t;
        if (j < NHID) {
            float hp0 = h0 ? pd[j] + a0[j] * i0 : 0.f;
            float hp1 = h1 ? pd[200 + j] + a1[j] * i1 : 0.f;
            float v0 = hp0 > 0.f ? hp0 : (__expf(hp0) - 1.f);
            float v1 = hp1 > 0.f ? hp1 : (__expf(hp1) - 1.f);
            bf16 hh, ll;
            split_bf16(v0, hh, ll); xh[j] = hh; xl[j] = ll;
            split_bf16(v1, hh, ll); xh[100 + j] = hh; xl[100 + j] = ll;
            d2 += v0 * g_w2[j]       + v1 * g_w2[100 + j];
            s2 += v0 * g_w2[200 + j] + v1 * g_w2[300 + j];
        }
    }
    int jp = 200 + lane;
    if (jp < K_PAD) { xh[jp] = __float2bfloat16_rn(0.f); xl[jp] = __float2bfloat16_rn(0.f); }
    d2 = warp_sum(d2); s2 = warp_sum(s2);
    if (lane == 0) { g_d2[n] = d2; g_s2[n] = s2; }
}

// ---------------- edge scatter, layer 2 ----------------
__global__ void edge_scatter2() {
    int gw = (blockIdx.x * blockDim.x + threadIdx.x) >> 5;
    int lane = threadIdx.x & 31;
    if (gw >= E_ALL) return;
    int d = g_dst[gw], s = g_src[gw], ra = g_rA[gw], rb = g_rB[gw];
    float dot = g_d2[d] + g_s2[s] + g_r2[ra];
    if (rb >= 0) dot += g_r2[rb];
    float lr = dot > 0.f ? dot : 0.2f * dot;
    float ev = __expf(-lr);
    const float* ps = g_proj2 + (size_t)s * 400 + 200;
    const float* rp = g_relproj2 + ra * DIM;
    const float* rpb = (rb >= 0) ? g_relproj2 + rb * DIM : nullptr;
    float* accrow = g_acc2 + (size_t)d * DIM;
    if (lane == 0) atomicAdd(&g_rowsum2[d], ev);
    #pragma unroll
    for (int t = 0; t < 7; t++) {
        int j = lane + 32 * t;
        if (j < DIM) {
            float v = ps[j] + rp[j];
            if (rpb) v += rpb[j];
            atomicAdd(&accrow[j], ev * v);
        }
    }
}

// ---------------- finalize: out_ent = l2norm(entlin + mask*elu(hp)) --------
__global__ void finalize(float* __restrict__ out) {
    int n = (blockIdx.x * blockDim.x + threadIdx.x) >> 5;
    int lane = threadIdx.x & 31;
    if (n >= N_NODES) return;
    float rs = g_rowsum2[n];
    bool has = rs != 0.f;
    float iS = has ? 1.f / rs : 0.f;
    float mk = g_mask[n];
    const float* pd = g_proj2 + (size_t)n * 400;
    const float* lin = g_projA + (size_t)n * 600 + 400;
    const float* acc = g_acc2 + (size_t)n * DIM;
    float v[7];
    float ss = 0.f;
    #pragma unroll
    for (int t = 0; t < 7; t++) {
        int j = lane + 32 * t;
        float val = 0.f;
        if (j < DIM) {
            float hp = has ? pd[j] + acc[j] * iS : 0.f;
            float el = hp > 0.f ? hp : (expf(hp) - 1.f);
            val = lin[j] + mk * el;
            ss += val * val;
        }
        v[t] = val;
    }
    ss = warp_sum(ss);
    float sc = 1.f / fmaxf(sqrtf(ss), 1e-12f);
    #pragma unroll
    for (int t = 0; t < 7; t++) {
        int j = lane + 32 * t;
        if (j < DIM) out[(size_t)n * DIM + j] = v[t] * sc;
    }
}

__global__ void copy_tail(float* __restrict__ out) {
    int i = blockIdx.x * blockDim.x + threadIdx.x;
    const size_t base = (size_t)N_NODES * DIM;
    if (i < N_RELS * DIM) out[base + i] = g_outrel[i];
    if (i < N_NODES) out[base + N_RELS * DIM + i] = g_mask[i];
}

// ---------------- launch ----------------
extern "C" void kernel_launch(void* const* d_in, const int* in_sizes, int n_in,
                              void* d_out, int out_size) {
    const float* ent   = (const float*)d_in[0];
    const float* rel   = (const float*)d_in[1];
    const float* W_ent = (const float*)d_in[2];
    const float* W_gat = (const float*)d_in[3];
    const float* a_h   = (const float*)d_in[4];
    const float* a2_h  = (const float*)d_in[5];
    const float* a_o   = (const float*)d_in[6];
    const float* a2_o  = (const float*)d_in[7];
    const int*   batch = (const int*)d_in[8];
    const int*   elist = (const int*)d_in[9];
    const int*   etype = (const int*)d_in[10];
    const int*   nhop  = (const int*)d_in[11];
    float* out = (float*)d_out;
    int n_batch = in_sizes[8];

    const int PREP_N = (600 * K_PAD > E_ALL) ? 600 * K_PAD : E_ALL;

    cudaFuncSetAttribute(gemm_bf16s<0>, cudaFuncAttributeMaxDynamicSharedMemorySize, SMEM_BYTES);
    cudaFuncSetAttribute(gemm_bf16s<1>, cudaFuncAttributeMaxDynamicSharedMemorySize, SMEM_BYTES);

    fold_w<<<(NHEADS * 600 + 255) / 256, 256>>>(a_h, a2_h, a_o, a2_o);          // 0
    prep<<<(PREP_N + 255) / 256, 256>>>(a_h, a_o, W_ent, elist, etype, nhop);   // 1
    l2norm_conv<<<(N_NODES * 32 + 255) / 256, 256>>>(ent);                      // 2

    {   // 3 — projA = [x@Bcat1^T | x@W_ent]  (profiled launch slot)
        dim3 grid((600 + GBN - 1) / GBN, (N_NODES + GBM - 1) / GBM);
        gemm_bf16s<0><<<grid, 256, SMEM_BYTES>>>();
    }

    zero_all<<<4096, 256>>>();                                                  // 4
    mask_scatter<<<(n_batch + 255) / 256, 256>>>(batch, n_batch);               // 5
    relproj1_k<<<(NHEADS * N_RELS * NHID + 255) / 256, 256>>>(rel, a_h);        // 6
    outrel_k<<<(N_RELS * DIM + 255) / 256, 256>>>(rel, W_gat);                  // 7
    relproj2_k<<<(N_RELS * DIM + 255) / 256, 256>>>(a_o);                       // 8
    rel_scalars<<<(NHEADS * N_RELS + 255) / 256, 256>>>(rel);                   // 9

    {
        dim3 grid((E_ALL + 7) / 8, 1);
        edge_scatter1<<<grid, 256>>>();                                         // 10
    }
    combine1<<<(N_NODES * 32 + 255) / 256, 256>>>();                            // 11

    {   // proj2 = x1 @ Bcat2^T
        dim3 grid((400 + GBN - 1) / GBN, (N_NODES + GBM - 1) / GBM);
        gemm_bf16s<1><<<grid, 256, SMEM_BYTES>>>();                             // 12
    }

    {
        dim3 grid((E_ALL + 7) / 8, 1);
        edge_scatter2<<<grid, 256>>>();                                         // 13
    }

    finalize<<<(N_NODES * 32 + 255) / 256, 256>>>(out);                         // 14
    copy_tail<<<(N_RELS * DIM + 255) / 256, 256>>>(out);                        // 15
}

// round 10
// speedup vs baseline: 1.9467x; 1.0355x over previous
#include <cuda_runtime.h>
#include <cuda_bf16.h>
#include <math.h>
#include <stdint.h>

#define N_NODES 50000
#define DIM     200
#define K_PAD   224
#define N_RELS  500
#define NHID    100
#define NHEADS  2
#define E_BASE  150000
#define E_NHOP  30000
#define E_ALL   180000

typedef __nv_bfloat16 bf16;

// ---------------- scratch (static device globals; no allocs) ----------------
__device__ __align__(16) bf16 g_xh[N_NODES * K_PAD];
__device__ __align__(16) bf16 g_xl[N_NODES * K_PAD];
__device__ __align__(16) bf16 g_x1h[N_NODES * K_PAD];
__device__ __align__(16) bf16 g_x1l[N_NODES * K_PAD];
__device__ __align__(16) bf16 g_BAh[600 * K_PAD];
__device__ __align__(16) bf16 g_BAl[600 * K_PAD];
__device__ __align__(16) bf16 g_B2h[400 * K_PAD];
__device__ __align__(16) bf16 g_B2l[400 * K_PAD];
__device__ __align__(16) float g_relproj1[NHEADS * N_RELS * NHID];
__device__ __align__(16) float g_projA[N_NODES * 600];   // cols 0-399: proj1, 400-599: entlin
__device__ int   g_dst[E_ALL];
__device__ int   g_src[E_ALL];
__device__ int   g_rA[E_ALL];
__device__ int   g_rB[E_ALL];
__device__ float g_rowsum1[NHEADS * N_NODES];
__device__ __align__(16) float g_acc1[NHEADS * N_NODES * NHID];
__device__ float g_outrel[N_RELS * DIM];
__device__ __align__(16) float g_relproj2[N_RELS * DIM];
__device__ __align__(16) float g_proj2[N_NODES * 400];
__device__ float g_rowsum2[N_NODES];
__device__ __align__(16) float g_acc2[N_NODES * DIM];
__device__ float g_mask[N_NODES];
// attention-scalar machinery
__device__ float g_w1[NHEADS * 600];
__device__ float g_w2[600];
__device__ float g_d1[NHEADS * N_NODES];
__device__ float g_s1[NHEADS * N_NODES];
__device__ float g_r1[NHEADS * N_RELS];
__device__ float g_d2[N_NODES];
__device__ float g_s2[N_NODES];
__device__ float g_r2[N_RELS];

// ---------------- helpers ----------------
__device__ __forceinline__ float warp_sum(float v) {
    #pragma unroll
    for (int o = 16; o; o >>= 1) v += __shfl_xor_sync(0xFFFFFFFFu, v, o);
    return v;
}

__device__ __forceinline__ void split_bf16(float x, bf16& hi, bf16& lo) {
    hi = __float2bfloat16_rn(x);
    lo = __float2bfloat16_rn(x - __bfloat162float(hi));
}

__device__ __forceinline__ void red_add_v4(float* addr, float4 v) {
    asm volatile("red.global.add.v4.f32 [%0], {%1,%2,%3,%4};"
                 :: "l"(addr), "f"(v.x), "f"(v.y), "f"(v.z), "f"(v.w) : "memory");
}
__device__ __forceinline__ void red_add_f32(float* addr, float v) {
    asm volatile("red.global.add.f32 [%0], %1;" :: "l"(addr), "f"(v) : "memory");
}

#define LDSM_X4(R, addr) asm volatile( \
    "ldmatrix.sync.aligned.m8n8.x4.shared.b16 {%0,%1,%2,%3}, [%4];" \
    : "=r"((R)[0]), "=r"((R)[1]), "=r"((R)[2]), "=r"((R)[3]) : "r"(addr))
#define LDSM_X2(R, addr) asm volatile( \
    "ldmatrix.sync.aligned.m8n8.x2.shared.b16 {%0,%1}, [%2];" \
    : "=r"((R)[0]), "=r"((R)[1]) : "r"(addr))
#define MMA_BF16(C, A, B) asm volatile( \
    "mma.sync.aligned.m16n8k16.row.col.f32.bf16.bf16.f32 " \
    "{%0,%1,%2,%3}, {%4,%5,%6,%7}, {%8,%9}, {%0,%1,%2,%3};" \
    : "+f"((C)[0]), "+f"((C)[1]), "+f"((C)[2]), "+f"((C)[3]) \
    : "r"((A)[0]), "r"((A)[1]), "r"((A)[2]), "r"((A)[3]), "r"((B)[0]), "r"((B)[1]))

__device__ __forceinline__ void cp_async16(uint32_t dst, const void* src, int szbytes) {
    asm volatile("cp.async.cg.shared.global [%0], [%1], 16, %2;"
                 :: "r"(dst), "l"(src), "r"(szbytes));
}
#define CP_COMMIT() asm volatile("cp.async.commit_group;")
#define CP_WAIT(N)  asm volatile("cp.async.wait_group %0;" :: "n"(N))

// ---------------- folded attention vectors ----------------
__global__ void fold_w(const float* __restrict__ a_heads, const float* __restrict__ a2_h,
                       const float* __restrict__ a_out,   const float* __restrict__ a2_o) {
    int i = blockIdx.x * blockDim.x + threadIdx.x;
    if (i < NHEADS * 600) {
        int h = i / 600, k = i % 600;
        float s = 0.f;
        for (int j = 0; j < NHID; j++) s += a_heads[(h * NHID + j) * 600 + k] * a2_h[h * NHID + j];
        g_w1[i] = s;
    }
    if (i < 600) {
        float s = 0.f;
        for (int j = 0; j < 200; j++) s += a_out[j * 600 + i] * a2_o[j];
        g_w2[i] = s;
    }
}

// ---------------- prep: B-matrix bf16 splits + edge arrays ----------------
// grid must cover max(600*K_PAD, E_ALL) threads
__global__ void prep(const float* __restrict__ a_heads,
                     const float* __restrict__ a_out,
                     const float* __restrict__ W_ent,
                     const int* __restrict__ edge_list,
                     const int* __restrict__ edge_type,
                     const int* __restrict__ nhop) {
    int i = blockIdx.x * blockDim.x + threadIdx.x;
    if (i < 600 * K_PAD) {
        int j = i / K_PAD, k = i % K_PAD;
        float v = 0.f;
        if (k < DIM) {
            if (j < 400) {
                int h = j / 200, w = j % 200, sect = w / NHID, jr = w % NHID;
                v = a_heads[(h * NHID + jr) * 600 + sect * DIM + k];
            } else {
                v = W_ent[k * DIM + (j - 400)];
            }
        }
        bf16 hi, lo; split_bf16(v, hi, lo);
        g_BAh[i] = hi; g_BAl[i] = lo;
        if (i < 400 * K_PAD) {
            float v2 = 0.f;
            if (k < DIM) v2 = a_out[(j % 200) * 600 + (j / 200) * DIM + k];
            bf16 h2, l2; split_bf16(v2, h2, l2);
            g_B2h[i] = h2; g_B2l[i] = l2;
        }
    }
    if (i < E_ALL) {
        if (i < E_BASE) {
            g_dst[i] = edge_list[i];
            g_src[i] = edge_list[E_BASE + i];
            g_rA[i]  = edge_type[i];
            g_rB[i]  = -1;
        } else {
            int t = i - E_BASE;
            g_dst[i] = nhop[t * 4 + 3];
            g_src[i] = nhop[t * 4 + 0];
            g_rA[i]  = nhop[t * 4 + 1];
            g_rB[i]  = nhop[t * 4 + 2];
        }
    }
}

// ---------------- l2norm + bf16 split + layer-1 node scalars (fused) ------
__global__ void l2norm_conv(const float* __restrict__ in) {
    int n = (blockIdx.x * blockDim.x + threadIdx.x) >> 5;
    int lane = threadIdx.x & 31;
    if (n >= N_NODES) return;
    const float* r = in + (size_t)n * DIM;
    float v[7];
    float ss = 0.f;
    #pragma unroll
    for (int t = 0; t < 7; t++) {
        int j = lane + 32 * t;
        float x = (j < DIM) ? r[j] : 0.f;
        v[t] = x; ss += x * x;
    }
    ss = warp_sum(ss);
    float sc = 1.f / fmaxf(sqrtf(ss), 1e-12f);
    float a = 0.f, b = 0.f, c = 0.f, d = 0.f;
    bf16* xh = g_xh + (size_t)n * K_PAD;
    bf16* xl = g_xl + (size_t)n * K_PAD;
    #pragma unroll
    for (int t = 0; t < 7; t++) {
        int j = lane + 32 * t;
        if (j < K_PAD) {
            float xv = (j < DIM) ? v[t] * sc : 0.f;
            bf16 hi, lo; split_bf16(xv, hi, lo);
            xh[j] = hi; xl[j] = lo;
            if (j < DIM) {
                a += xv * g_w1[j];
                b += xv * g_w1[200 + j];
                c += xv * g_w1[600 + j];
                d += xv * g_w1[800 + j];
            }
        }
    }
    a = warp_sum(a); b = warp_sum(b); c = warp_sum(c); d = warp_sum(d);
    if (lane == 0) {
        g_d1[n] = a; g_s1[n] = b;
        g_d1[N_NODES + n] = c; g_s1[N_NODES + n] = d;
    }
}

// ---------------- zero accumulators (vectorized) ----------------
__global__ void zero_all() {
    int stride = gridDim.x * blockDim.x;
    int tid = blockIdx.x * blockDim.x + threadIdx.x;
    const int N1 = NHEADS * N_NODES * NHID / 4;   // acc1 in float4
    const int N2 = N_NODES * DIM / 4;             // acc2 in float4
    float4 z = make_float4(0.f, 0.f, 0.f, 0.f);
    for (int i = tid; i < N1; i += stride) {
        ((float4*)g_acc1)[i] = z;
        if (i < N2) ((float4*)g_acc2)[i] = z;
        if (i < NHEADS * N_NODES) g_rowsum1[i] = 0.f;
        if (i < N_NODES) { g_rowsum2[i] = 0.f; g_mask[i] = 0.f; }
    }
}

__global__ void mask_scatter(const int* __restrict__ batch, int n) {
    int i = blockIdx.x * blockDim.x + threadIdx.x;
    if (i < n) g_mask[batch[i]] = 1.0f;
}

// ---------------- relation projections (fp32, small) ----------------
__global__ void relproj1_k(const float* __restrict__ rel, const float* __restrict__ a_heads) {
    int i = blockIdx.x * blockDim.x + threadIdx.x;
    if (i >= NHEADS * N_RELS * NHID) return;
    int h = i / (N_RELS * NHID);
    int rem = i % (N_RELS * NHID);
    int r = rem / NHID, j = rem % NHID;
    const float* ar = a_heads + (h * NHID + j) * 600 + 400;
    const float* rr = rel + r * DIM;
    float s = 0.f;
    #pragma unroll 4
    for (int k = 0; k < DIM; k++) s += rr[k] * ar[k];
    g_relproj1[i] = s;
}

__global__ void outrel_k(const float* __restrict__ rel, const float* __restrict__ W_gat) {
    int i = blockIdx.x * blockDim.x + threadIdx.x;
    if (i >= N_RELS * DIM) return;
    int r = i / DIM, j = i % DIM;
    const float* rr = rel + r * DIM;
    float s = 0.f;
    #pragma unroll 4
    for (int k = 0; k < DIM; k++) s += rr[k] * W_gat[k * DIM + j];
    g_outrel[i] = s;
}

__global__ void relproj2_k(const float* __restrict__ a_out) {
    int i = blockIdx.x * blockDim.x + threadIdx.x;
    if (i >= N_RELS * DIM) return;
    int r = i / DIM, j = i % DIM;
    const float* rr = g_outrel + r * DIM;
    const float* ar = a_out + j * 600 + 400;
    float s = 0.f;
    #pragma unroll 4
    for (int k = 0; k < DIM; k++) s += rr[k] * ar[k];
    g_relproj2[i] = s;
}

__global__ void rel_scalars(const float* __restrict__ rel) {
    int i = blockIdx.x * blockDim.x + threadIdx.x;
    if (i < NHEADS * N_RELS) {
        int h = i / N_RELS, r = i % N_RELS;
        float s = 0.f;
        for (int k = 0; k < DIM; k++) s += rel[r * DIM + k] * g_w1[h * 600 + 400 + k];
        g_r1[i] = s;
    }
    if (i < N_RELS) {
        float s = 0.f;
        for (int k = 0; k < DIM; k++) s += g_outrel[i * DIM + k] * g_w2[400 + k];
        g_r2[i] = s;
    }
}

// ---------------- split-bf16 tensor GEMM with cp.async double buffering ----
#define GBM 128
#define GBN 128
#define GBK 32
#define SROW 40
#define TILE (GBM * SROW)
#define STAGE_ELEMS (4 * TILE)
#define SMEM_BYTES (2 * STAGE_ELEMS * 2)
#define NKCH (K_PAD / GBK)

extern __shared__ bf16 smem_dyn[];

template <int SEL>
__global__ __launch_bounds__(256, 2) void gemm_bf16s() {
    const bf16 *Ah, *Al, *Bh, *Bl; float* C; int M, Nn;
    if (SEL == 0) { Ah = g_xh;  Al = g_xl;  Bh = g_BAh; Bl = g_BAl; C = g_projA; M = N_NODES; Nn = 600; }
    else          { Ah = g_x1h; Al = g_x1l; Bh = g_B2h; Bl = g_B2l; C = g_proj2; M = N_NODES; Nn = 400; }

    int tid = threadIdx.x;
    int lane = tid & 31;
    int w = tid >> 5;
    int wm = (w & 3) * 32;
    int wn = (w >> 2) * 64;
    int row0 = blockIdx.y * GBM;
    int col0 = blockIdx.x * GBN;

    uint32_t ubase = (uint32_t)__cvta_generic_to_shared(smem_dyn);

    int r_ld[2], c8_ld[2];
    #pragma unroll
    for (int i = 0; i < 2; i++) { int idx = tid + 256 * i; r_ld[i] = idx >> 2; c8_ld[i] = (idx & 3) * 8; }
    bool aok[2], bok[2];
    #pragma unroll
    for (int i = 0; i < 2; i++) { aok[i] = (row0 + r_ld[i]) < M; bok[i] = (col0 + r_ld[i]) < Nn; }

    float acc[2][8][4];
    #pragma unroll
    for (int mt = 0; mt < 2; mt++)
        #pragma unroll
        for (int nt = 0; nt < 8; nt++)
            #pragma unroll
            for (int q = 0; q < 4; q++) acc[mt][nt][q] = 0.f;

    auto load_stage = [&](int s, int k0) {
        uint32_t sb = ubase + (uint32_t)(s * STAGE_ELEMS) * 2;
        #pragma unroll
        for (int i = 0; i < 2; i++) {
            int r = r_ld[i], c8 = c8_ld[i];
            uint32_t doff = (uint32_t)(r * SROW + c8) * 2;
            size_t arow = (size_t)(row0 + r) * K_PAD + k0 + c8;
            size_t brow = (size_t)(col0 + r) * K_PAD + k0 + c8;
            cp_async16(sb + 0 * TILE * 2 + doff, Ah + arow, aok[i] ? 16 : 0);
            cp_async16(sb + 1 * TILE * 2 + doff, Al + arow, aok[i] ? 16 : 0);
            cp_async16(sb + 2 * TILE * 2 + doff, Bh + brow, bok[i] ? 16 : 0);
            cp_async16(sb + 3 * TILE * 2 + doff, Bl + brow, bok[i] ? 16 : 0);
        }
        CP_COMMIT();
    };

    load_stage(0, 0);

    for (int kt = 0; kt < NKCH; kt++) {
        if (kt + 1 < NKCH) load_stage((kt + 1) & 1, (kt + 1) * GBK);
        if (kt + 1 < NKCH) { CP_WAIT(1); } else { CP_WAIT(0); }
        __syncthreads();

        uint32_t sb = ubase + (uint32_t)((kt & 1) * STAGE_ELEMS) * 2;
        uint32_t uAh = sb;
        uint32_t uAl = sb + TILE * 2;
        uint32_t uBh = sb + 2 * TILE * 2;
        uint32_t uBl = sb + 3 * TILE * 2;

        #pragma unroll
        for (int k16 = 0; k16 < GBK; k16 += 16) {
            uint32_t ah[2][4], al[2][4];
            #pragma unroll
            for (int mt = 0; mt < 2; mt++) {
                uint32_t off = (uint32_t)((wm + mt * 16 + (lane & 15)) * SROW + k16 + (lane >> 4) * 8) * 2;
                LDSM_X4(ah[mt], uAh + off);
                LDSM_X4(al[mt], uAl + off);
            }
            #pragma unroll
            for (int nt = 0; nt < 8; nt++) {
                uint32_t boff = (uint32_t)((wn + nt * 8 + (lane & 7)) * SROW + k16 + ((lane >> 3) & 1) * 8) * 2;
                uint32_t bh[2], bl[2];
                LDSM_X2(bh, uBh + boff);
                LDSM_X2(bl, uBl + boff);
                #pragma unroll
                for (int mt = 0; mt < 2; mt++) {
                    MMA_BF16(acc[mt][nt], ah[mt], bh);
                    MMA_BF16(acc[mt][nt], ah[mt], bl);
                    MMA_BF16(acc[mt][nt], al[mt], bh);
                }
            }
        }
        __syncthreads();
    }

    #pragma unroll
    for (int mt = 0; mt < 2; mt++) {
        int r0 = row0 + wm + mt * 16 + (lane >> 2);
        #pragma unroll
        for (int nt = 0; nt < 8; nt++) {
            int c = col0 + wn + nt * 8 + (lane & 3) * 2;
            if (c < Nn) {
                if (r0 < M)
                    *(float2*)(C + (size_t)r0 * Nn + c) = make_float2(acc[mt][nt][0], acc[mt][nt][1]);
                if (r0 + 8 < M)
                    *(float2*)(C + (size_t)(r0 + 8) * Nn + c) = make_float2(acc[mt][nt][2], acc[mt][nt][3]);
            }
        }
    }
}

// ---------------- edge scatter, layer 1 (warp per edge, both heads, v4 red) -
__global__ void edge_scatter1() {
    int gw = (blockIdx.x * blockDim.x + threadIdx.x) >> 5;
    int lane = threadIdx.x & 31;
    if (gw >= E_ALL) return;
    int d = g_dst[gw], s = g_src[gw], ra = g_rA[gw], rb = g_rB[gw];
    float dot0 = g_d1[d] + g_s1[s] + g_r1[ra];
    float dot1 = g_d1[N_NODES + d] + g_s1[N_NODES + s] + g_r1[N_RELS + ra];
    if (rb >= 0) { dot0 += g_r1[rb]; dot1 += g_r1[N_RELS + rb]; }
    float lr0 = dot0 > 0.f ? dot0 : 0.2f * dot0;
    float lr1 = dot1 > 0.f ? dot1 : 0.2f * dot1;
    float ev0 = __expf(-lr0);
    float ev1 = __expf(-lr1);
    if (lane == 0) {
        red_add_f32(&g_rowsum1[d], ev0);
        red_add_f32(&g_rowsum1[N_NODES + d], ev1);
    }
    // 50 float4 work items: q<25 -> head0 chunk q, else head1 chunk q-25
    #pragma unroll
    for (int it = 0; it < 2; it++) {
        int q = lane + 32 * it;
        if (q < 50) {
            int h = (q < 25) ? 0 : 1;
            int c4 = (q < 25) ? q : q - 25;
            float ev = h ? ev1 : ev0;
            const float4* ps = (const float4*)(g_projA + (size_t)s * 600 + h * 200 + 100);
            const float4* rp = (const float4*)(g_relproj1 + (h * N_RELS + ra) * NHID);
            float4 v = ps[c4];
            float4 r = rp[c4];
            v.x += r.x; v.y += r.y; v.z += r.z; v.w += r.w;
            if (rb >= 0) {
                const float4* rp2 = (const float4*)(g_relproj1 + (h * N_RELS + rb) * NHID);
                float4 r2 = rp2[c4];
                v.x += r2.x; v.y += r2.y; v.z += r2.z; v.w += r2.w;
            }
            v.x *= ev; v.y *= ev; v.z *= ev; v.w *= ev;
            red_add_v4(g_acc1 + ((size_t)h * N_NODES + d) * NHID + c4 * 4, v);
        }
    }
}

// ---------------- combine layer-1 -> x1 split + layer-2 node scalars -------
__global__ void combine1() {
    int n = (blockIdx.x * blockDim.x + threadIdx.x) >> 5;
    int lane = threadIdx.x & 31;
    if (n >= N_NODES) return;
    float rs0 = g_rowsum1[n];
    float rs1 = g_rowsum1[N_NODES + n];
    bool h0 = rs0 != 0.f, h1 = rs1 != 0.f;
    float i0 = h0 ? 1.f / rs0 : 0.f;
    float i1 = h1 ? 1.f / rs1 : 0.f;
    const float* pd = g_projA + (size_t)n * 600;
    const float* a0 = g_acc1 + (size_t)n * NHID;
    const float* a1 = g_acc1 + ((size_t)N_NODES + n) * NHID;
    bf16* xh = g_x1h + (size_t)n * K_PAD;
    bf16* xl = g_x1l + (size_t)n * K_PAD;
    float d2 = 0.f, s2 = 0.f;
    #pragma unroll
    for (int t = 0; t < 4; t++) {
        int j = lane + 32 * t;
        if (j < NHID) {
            float hp0 = h0 ? pd[j] + a0[j] * i0 : 0.f;
            float hp1 = h1 ? pd[200 + j] + a1[j] * i1 : 0.f;
            float v0 = hp0 > 0.f ? hp0 : (__expf(hp0) - 1.f);
            float v1 = hp1 > 0.f ? hp1 : (__expf(hp1) - 1.f);
            bf16 hh, ll;
            split_bf16(v0, hh, ll); xh[j] = hh; xl[j] = ll;
            split_bf16(v1, hh, ll); xh[100 + j] = hh; xl[100 + j] = ll;
            d2 += v0 * g_w2[j]       + v1 * g_w2[100 + j];
            s2 += v0 * g_w2[200 + j] + v1 * g_w2[300 + j];
        }
    }
    int jp = 200 + lane;
    if (jp < K_PAD) { xh[jp] = __float2bfloat16_rn(0.f); xl[jp] = __float2bfloat16_rn(0.f); }
    d2 = warp_sum(d2); s2 = warp_sum(s2);
    if (lane == 0) { g_d2[n] = d2; g_s2[n] = s2; }
}

// ---------------- edge scatter, layer 2 (v4 red) ----------------
__global__ void edge_scatter2() {
    int gw = (blockIdx.x * blockDim.x + threadIdx.x) >> 5;
    int lane = threadIdx.x & 31;
    if (gw >= E_ALL) return;
    int d = g_dst[gw], s = g_src[gw], ra = g_rA[gw], rb = g_rB[gw];
    float dot = g_d2[d] + g_s2[s] + g_r2[ra];
    if (rb >= 0) dot += g_r2[rb];
    float lr = dot > 0.f ? dot : 0.2f * dot;
    float ev = __expf(-lr);
    if (lane == 0) red_add_f32(&g_rowsum2[d], ev);
    const float4* ps = (const float4*)(g_proj2 + (size_t)s * 400 + 200);
    const float4* rp = (const float4*)(g_relproj2 + (size_t)ra * DIM);
    const float4* rpb = (rb >= 0) ? (const float4*)(g_relproj2 + (size_t)rb * DIM) : nullptr;
    float* accrow = g_acc2 + (size_t)d * DIM;
    #pragma unroll
    for (int it = 0; it < 2; it++) {
        int q = lane + 32 * it;
        if (q < 50) {
            float4 v = ps[q];
            float4 r = rp[q];
            v.x += r.x; v.y += r.y; v.z += r.z; v.w += r.w;
            if (rpb) {
                float4 r2 = rpb[q];
                v.x += r2.x; v.y += r2.y; v.z += r2.z; v.w += r2.w;
            }
            v.x *= ev; v.y *= ev; v.z *= ev; v.w *= ev;
            red_add_v4(accrow + q * 4, v);
        }
    }
}

// ---------------- finalize: out_ent = l2norm(entlin + mask*elu(hp)) --------
__global__ void finalize(float* __restrict__ out) {
    int n = (blockIdx.x * blockDim.x + threadIdx.x) >> 5;
    int lane = threadIdx.x & 31;
    if (n >= N_NODES) return;
    float rs = g_rowsum2[n];
    bool has = rs != 0.f;
    float iS = has ? 1.f / rs : 0.f;
    float mk = g_mask[n];
    const float* pd = g_proj2 + (size_t)n * 400;
    const float* lin = g_projA + (size_t)n * 600 + 400;
    const float* acc = g_acc2 + (size_t)n * DIM;
    float v[7];
    float ss = 0.f;
    #pragma unroll
    for (int t = 0; t < 7; t++) {
        int j = lane + 32 * t;
        float val = 0.f;
        if (j < DIM) {
            float hp = has ? pd[j] + acc[j] * iS : 0.f;
            float el = hp > 0.f ? hp : (expf(hp) - 1.f);
            val = lin[j] + mk * el;
            ss += val * val;
        }
        v[t] = val;
    }
    ss = warp_sum(ss);
    float sc = 1.f / fmaxf(sqrtf(ss), 1e-12f);
    #pragma unroll
    for (int t = 0; t < 7; t++) {
        int j = lane + 32 * t;
        if (j < DIM) out[(size_t)n * DIM + j] = v[t] * sc;
    }
}

__global__ void copy_tail(float* __restrict__ out) {
    int i = blockIdx.x * blockDim.x + threadIdx.x;
    const size_t base = (size_t)N_NODES * DIM;
    if (i < N_RELS * DIM) out[base + i] = g_outrel[i];
    if (i < N_NODES) out[base + N_RELS * DIM + i] = g_mask[i];
}

// ---------------- launch ----------------
extern "C" void kernel_launch(void* const* d_in, const int* in_sizes, int n_in,
                              void* d_out, int out_size) {
    const float* ent   = (const float*)d_in[0];
    const float* rel   = (const float*)d_in[1];
    const float* W_ent = (const float*)d_in[2];
    const float* W_gat = (const float*)d_in[3];
    const float* a_h   = (const float*)d_in[4];
    const float* a2_h  = (const float*)d_in[5];
    const float* a_o   = (const float*)d_in[6];
    const float* a2_o  = (const float*)d_in[7];
    const int*   batch = (const int*)d_in[8];
    const int*   elist = (const int*)d_in[9];
    const int*   etype = (const int*)d_in[10];
    const int*   nhop  = (const int*)d_in[11];
    float* out = (float*)d_out;
    int n_batch = in_sizes[8];

    const int PREP_N = (600 * K_PAD > E_ALL) ? 600 * K_PAD : E_ALL;

    cudaFuncSetAttribute(gemm_bf16s<0>, cudaFuncAttributeMaxDynamicSharedMemorySize, SMEM_BYTES);
    cudaFuncSetAttribute(gemm_bf16s<1>, cudaFuncAttributeMaxDynamicSharedMemorySize, SMEM_BYTES);

    fold_w<<<(NHEADS * 600 + 255) / 256, 256>>>(a_h, a2_h, a_o, a2_o);          // 0
    prep<<<(PREP_N + 255) / 256, 256>>>(a_h, a_o, W_ent, elist, etype, nhop);   // 1
    l2norm_conv<<<(N_NODES * 32 + 255) / 256, 256>>>(ent);                      // 2

    {   // 3 — projA = [x@Bcat1^T | x@W_ent]  (profiled launch slot)
        dim3 grid((600 + GBN - 1) / GBN, (N_NODES + GBM - 1) / GBM);
        gemm_bf16s<0><<<grid, 256, SMEM_BYTES>>>();
    }

    zero_all<<<2048, 256>>>();                                                  // 4
    mask_scatter<<<(n_batch + 255) / 256, 256>>>(batch, n_batch);               // 5
    relproj1_k<<<(NHEADS * N_RELS * NHID + 255) / 256, 256>>>(rel, a_h);        // 6
    outrel_k<<<(N_RELS * DIM + 255) / 256, 256>>>(rel, W_gat);                  // 7
    relproj2_k<<<(N_RELS * DIM + 255) / 256, 256>>>(a_o);                       // 8
    rel_scalars<<<(NHEADS * N_RELS + 255) / 256, 256>>>(rel);                   // 9

    {
        dim3 grid((E_ALL + 7) / 8, 1);
        edge_scatter1<<<grid, 256>>>();                                         // 10
    }
    combine1<<<(N_NODES * 32 + 255) / 256, 256>>>();                            // 11

    {   // proj2 = x1 @ Bcat2^T
        dim3 grid((400 + GBN - 1) / GBN, (N_NODES + GBM - 1) / GBM);
        gemm_bf16s<1><<<grid, 256, SMEM_BYTES>>>();                             // 12
    }

    {
        dim3 grid((E_ALL + 7) / 8, 1);
        edge_scatter2<<<grid, 256>>>();                                         // 13
    }

    finalize<<<(N_NODES * 32 + 255) / 256, 256>>>(out);                         // 14
    copy_tail<<<(N_RELS * DIM + 255) / 256, 256>>>(out);                        // 15
}

// round 11
// speedup vs baseline: 2.0961x; 1.0768x over previous
#include <cuda_runtime.h>
#include <cuda_bf16.h>
#include <math.h>
#include <stdint.h>

#define N_NODES 50000
#define DIM     200
#define K_PAD   224
#define N_RELS  500
#define NHID    100
#define NHEADS  2
#define E_BASE  150000
#define E_NHOP  30000
#define E_ALL   180000

typedef __nv_bfloat16 bf16;

// ---------------- scratch (static device globals; no allocs) ----------------
__device__ __align__(16) bf16 g_xh[N_NODES * K_PAD];
__device__ __align__(16) bf16 g_xl[N_NODES * K_PAD];
__device__ __align__(16) bf16 g_x1h[N_NODES * K_PAD];
__device__ __align__(16) bf16 g_x1l[N_NODES * K_PAD];
__device__ __align__(16) bf16 g_BAh[600 * K_PAD];
__device__ __align__(16) bf16 g_BAl[600 * K_PAD];
__device__ __align__(16) bf16 g_B2h[400 * K_PAD];
__device__ __align__(16) bf16 g_B2l[400 * K_PAD];
__device__ __align__(16) float g_relproj1[NHEADS * N_RELS * NHID];
__device__ __align__(16) float g_projA[N_NODES * 600];   // cols 0-399: proj1, 400-599: entlin
__device__ int   g_dst[E_ALL];
__device__ int   g_src[E_ALL];
__device__ int   g_rA[E_ALL];
__device__ int   g_rB[E_ALL];
__device__ float g_rowsum1[NHEADS * N_NODES];
__device__ __align__(16) float g_acc1[NHEADS * N_NODES * NHID];
__device__ float g_outrel[N_RELS * DIM];
__device__ __align__(16) float g_relproj2[N_RELS * DIM];
__device__ __align__(16) float g_proj2[N_NODES * 400];
__device__ float g_rowsum2[N_NODES];
__device__ __align__(16) float g_acc2[N_NODES * DIM];
__device__ float g_mask[N_NODES];
// attention-scalar machinery
__device__ float g_w1[NHEADS * 600];
__device__ float g_w2[600];
__device__ float g_d1[NHEADS * N_NODES];
__device__ float g_s1[NHEADS * N_NODES];
__device__ float g_r1[NHEADS * N_RELS];
__device__ float g_d2[N_NODES];
__device__ float g_s2[N_NODES];
__device__ float g_r2[N_RELS];

// ---------------- helpers ----------------
__device__ __forceinline__ float warp_sum(float v) {
    #pragma unroll
    for (int o = 16; o; o >>= 1) v += __shfl_xor_sync(0xFFFFFFFFu, v, o);
    return v;
}

__device__ __forceinline__ void split_bf16(float x, bf16& hi, bf16& lo) {
    hi = __float2bfloat16_rn(x);
    lo = __float2bfloat16_rn(x - __bfloat162float(hi));
}

__device__ __forceinline__ void red_add_v4(float* addr, float4 v) {
    asm volatile("red.global.add.v4.f32 [%0], {%1,%2,%3,%4};"
                 :: "l"(addr), "f"(v.x), "f"(v.y), "f"(v.z), "f"(v.w) : "memory");
}
__device__ __forceinline__ void red_add_f32(float* addr, float v) {
    asm volatile("red.global.add.f32 [%0], %1;" :: "l"(addr), "f"(v) : "memory");
}

#define LDSM_X4(R, addr) asm volatile( \
    "ldmatrix.sync.aligned.m8n8.x4.shared.b16 {%0,%1,%2,%3}, [%4];" \
    : "=r"((R)[0]), "=r"((R)[1]), "=r"((R)[2]), "=r"((R)[3]) : "r"(addr))
#define MMA_BF16(C, A, B) asm volatile( \
    "mma.sync.aligned.m16n8k16.row.col.f32.bf16.bf16.f32 " \
    "{%0,%1,%2,%3}, {%4,%5,%6,%7}, {%8,%9}, {%0,%1,%2,%3};" \
    : "+f"((C)[0]), "+f"((C)[1]), "+f"((C)[2]), "+f"((C)[3]) \
    : "r"((A)[0]), "r"((A)[1]), "r"((A)[2]), "r"((A)[3]), "r"((B)[0]), "r"((B)[1]))

__device__ __forceinline__ void cp_async16(uint32_t dst, const void* src, int szbytes) {
    asm volatile("cp.async.cg.shared.global [%0], [%1], 16, %2;"
                 :: "r"(dst), "l"(src), "r"(szbytes));
}
#define CP_COMMIT() asm volatile("cp.async.commit_group;")
#define CP_WAIT(N)  asm volatile("cp.async.wait_group %0;" :: "n"(N))

// ---------------- folded attention vectors + mask zero ----------------
__global__ void fold_w(const float* __restrict__ a_heads, const float* __restrict__ a2_h,
                       const float* __restrict__ a_out,   const float* __restrict__ a2_o) {
    int i = blockIdx.x * blockDim.x + threadIdx.x;
    if (i < NHEADS * 600) {
        int h = i / 600, k = i % 600;
        float s = 0.f;
        for (int j = 0; j < NHID; j++) s += a_heads[(h * NHID + j) * 600 + k] * a2_h[h * NHID + j];
        g_w1[i] = s;
    }
    if (i < 600) {
        float s = 0.f;
        for (int j = 0; j < 200; j++) s += a_out[j * 600 + i] * a2_o[j];
        g_w2[i] = s;
    }
    if (i < N_NODES) g_mask[i] = 0.f;
}

// ---------------- prep: B splits + edge arrays + mask scatter --------------
// grid must cover max(600*K_PAD, E_ALL) threads
__global__ void prep(const float* __restrict__ a_heads,
                     const float* __restrict__ a_out,
                     const float* __restrict__ W_ent,
                     const int* __restrict__ edge_list,
                     const int* __restrict__ edge_type,
                     const int* __restrict__ nhop,
                     const int* __restrict__ batch, int n_batch) {
    int i = blockIdx.x * blockDim.x + threadIdx.x;
    if (i < 600 * K_PAD) {
        int j = i / K_PAD, k = i % K_PAD;
        float v = 0.f;
        if (k < DIM) {
            if (j < 400) {
                int h = j / 200, w = j % 200, sect = w / NHID, jr = w % NHID;
                v = a_heads[(h * NHID + jr) * 600 + sect * DIM + k];
            } else {
                v = W_ent[k * DIM + (j - 400)];
            }
        }
        bf16 hi, lo; split_bf16(v, hi, lo);
        g_BAh[i] = hi; g_BAl[i] = lo;
        if (i < 400 * K_PAD) {
            float v2 = 0.f;
            if (k < DIM) v2 = a_out[(j % 200) * 600 + (j / 200) * DIM + k];
            bf16 h2, l2; split_bf16(v2, h2, l2);
            g_B2h[i] = h2; g_B2l[i] = l2;
        }
    }
    if (i < E_ALL) {
        if (i < E_BASE) {
            g_dst[i] = edge_list[i];
            g_src[i] = edge_list[E_BASE + i];
            g_rA[i]  = edge_type[i];
            g_rB[i]  = -1;
        } else {
            int t = i - E_BASE;
            g_dst[i] = nhop[t * 4 + 3];
            g_src[i] = nhop[t * 4 + 0];
            g_rA[i]  = nhop[t * 4 + 1];
            g_rB[i]  = nhop[t * 4 + 2];
        }
    }
    if (i < n_batch) g_mask[batch[i]] = 1.0f;   // fold_w zeroed mask (prior launch)
}

// ---------------- l2norm + bf16 split + layer-1 node scalars (fused) ------
__global__ void l2norm_conv(const float* __restrict__ in) {
    int n = (blockIdx.x * blockDim.x + threadIdx.x) >> 5;
    int lane = threadIdx.x & 31;
    if (n >= N_NODES) return;
    const float* r = in + (size_t)n * DIM;
    float v[7];
    float ss = 0.f;
    #pragma unroll
    for (int t = 0; t < 7; t++) {
        int j = lane + 32 * t;
        float x = (j < DIM) ? r[j] : 0.f;
        v[t] = x; ss += x * x;
    }
    ss = warp_sum(ss);
    float sc = 1.f / fmaxf(sqrtf(ss), 1e-12f);
    float a = 0.f, b = 0.f, c = 0.f, d = 0.f;
    bf16* xh = g_xh + (size_t)n * K_PAD;
    bf16* xl = g_xl + (size_t)n * K_PAD;
    #pragma unroll
    for (int t = 0; t < 7; t++) {
        int j = lane + 32 * t;
        if (j < K_PAD) {
            float xv = (j < DIM) ? v[t] * sc : 0.f;
            bf16 hi, lo; split_bf16(xv, hi, lo);
            xh[j] = hi; xl[j] = lo;
            if (j < DIM) {
                a += xv * g_w1[j];
                b += xv * g_w1[200 + j];
                c += xv * g_w1[600 + j];
                d += xv * g_w1[800 + j];
            }
        }
    }
    a = warp_sum(a); b = warp_sum(b); c = warp_sum(c); d = warp_sum(d);
    if (lane == 0) {
        g_d1[n] = a; g_s1[n] = b;
        g_d1[N_NODES + n] = c; g_s1[N_NODES + n] = d;
    }
}

// ---------------- zero accumulators (vectorized) ----------------
__global__ void zero_all() {
    int stride = gridDim.x * blockDim.x;
    int tid = blockIdx.x * blockDim.x + threadIdx.x;
    const int N1 = NHEADS * N_NODES * NHID / 4;
    const int N2 = N_NODES * DIM / 4;
    float4 z = make_float4(0.f, 0.f, 0.f, 0.f);
    for (int i = tid; i < N1; i += stride) {
        ((float4*)g_acc1)[i] = z;
        if (i < N2) ((float4*)g_acc2)[i] = z;
        if (i < NHEADS * N_NODES) g_rowsum1[i] = 0.f;
        if (i < N_NODES) g_rowsum2[i] = 0.f;
    }
}

// ---------------- rel kernel A: relproj1 + outrel + r1 ----------------
__global__ void relA(const float* __restrict__ rel, const float* __restrict__ a_heads,
                     const float* __restrict__ W_gat) {
    int i = blockIdx.x * blockDim.x + threadIdx.x;
    if (i < NHEADS * N_RELS * NHID) {
        int h = i / (N_RELS * NHID);
        int rem = i % (N_RELS * NHID);
        int r = rem / NHID, j = rem % NHID;
        const float* ar = a_heads + (h * NHID + j) * 600 + 400;
        const float* rr = rel + r * DIM;
        float s = 0.f;
        #pragma unroll 4
        for (int k = 0; k < DIM; k++) s += rr[k] * ar[k];
        g_relproj1[i] = s;
    }
    if (i < N_RELS * DIM) {
        int r = i / DIM, j = i % DIM;
        const float* rr = rel + r * DIM;
        float s = 0.f;
        #pragma unroll 4
        for (int k = 0; k < DIM; k++) s += rr[k] * W_gat[k * DIM + j];
        g_outrel[i] = s;
    }
    if (i < NHEADS * N_RELS) {
        int h = i / N_RELS, r = i % N_RELS;
        float s = 0.f;
        for (int k = 0; k < DIM; k++) s += rel[r * DIM + k] * g_w1[h * 600 + 400 + k];
        g_r1[i] = s;
    }
}

// ---------------- rel kernel B: relproj2 + r2 (needs outrel) ---------------
__global__ void relB(const float* __restrict__ a_out) {
    int i = blockIdx.x * blockDim.x + threadIdx.x;
    if (i < N_RELS * DIM) {
        int r = i / DIM, j = i % DIM;
        const float* rr = g_outrel + r * DIM;
        const float* ar = a_out + j * 600 + 400;
        float s = 0.f;
        #pragma unroll 4
        for (int k = 0; k < DIM; k++) s += rr[k] * ar[k];
        g_relproj2[i] = s;
    }
    if (i < N_RELS) {
        float s = 0.f;
        for (int k = 0; k < DIM; k++) s += g_outrel[i * DIM + k] * g_w2[400 + k];
        g_r2[i] = s;
    }
}

// ---------------- split-bf16 tensor GEMM, 2-stage cp.async, 1 sync/chunk ---
#define GBM 128
#define GBN 128
#define GBK 32
#define SROW 40
#define TILE (GBM * SROW)
#define STAGE_ELEMS (4 * TILE)
#define SMEM_BYTES (2 * STAGE_ELEMS * 2)
#define NKCH (K_PAD / GBK)

extern __shared__ bf16 smem_dyn[];

template <int SEL>
__global__ __launch_bounds__(256, 2) void gemm_bf16s() {
    const bf16 *Ah, *Al, *Bh, *Bl; float* C; int M, Nn;
    if (SEL == 0) { Ah = g_xh;  Al = g_xl;  Bh = g_BAh; Bl = g_BAl; C = g_projA; M = N_NODES; Nn = 600; }
    else          { Ah = g_x1h; Al = g_x1l; Bh = g_B2h; Bl = g_B2l; C = g_proj2; M = N_NODES; Nn = 400; }

    int tid = threadIdx.x;
    int lane = tid & 31;
    int w = tid >> 5;
    int wm = (w & 3) * 32;
    int wn = (w >> 2) * 64;
    int row0 = blockIdx.y * GBM;
    int col0 = blockIdx.x * GBN;

    uint32_t ubase = (uint32_t)__cvta_generic_to_shared(smem_dyn);

    int r_ld[2], c8_ld[2];
    #pragma unroll
    for (int i = 0; i < 2; i++) { int idx = tid + 256 * i; r_ld[i] = idx >> 2; c8_ld[i] = (idx & 3) * 8; }
    bool aok[2], bok[2];
    #pragma unroll
    for (int i = 0; i < 2; i++) { aok[i] = (row0 + r_ld[i]) < M; bok[i] = (col0 + r_ld[i]) < Nn; }

    float acc[2][8][4];
    #pragma unroll
    for (int mt = 0; mt < 2; mt++)
        #pragma unroll
        for (int nt = 0; nt < 8; nt++)
            #pragma unroll
            for (int q = 0; q < 4; q++) acc[mt][nt][q] = 0.f;

    auto load_stage = [&](int s, int k0) {
        uint32_t sb = ubase + (uint32_t)(s * STAGE_ELEMS) * 2;
        #pragma unroll
        for (int i = 0; i < 2; i++) {
            int r = r_ld[i], c8 = c8_ld[i];
            uint32_t doff = (uint32_t)(r * SROW + c8) * 2;
            size_t arow = (size_t)(row0 + r) * K_PAD + k0 + c8;
            size_t brow = (size_t)(col0 + r) * K_PAD + k0 + c8;
            cp_async16(sb + 0 * TILE * 2 + doff, Ah + arow, aok[i] ? 16 : 0);
            cp_async16(sb + 1 * TILE * 2 + doff, Al + arow, aok[i] ? 16 : 0);
            cp_async16(sb + 2 * TILE * 2 + doff, Bh + brow, bok[i] ? 16 : 0);
            cp_async16(sb + 3 * TILE * 2 + doff, Bl + brow, bok[i] ? 16 : 0);
        }
        CP_COMMIT();
    };

    load_stage(0, 0);

    // B fragment addressing for ldmatrix.x4 covering TWO n-tiles (16 cols):
    // lanes 0-7:   rows n+0..7  @ k16      -> frag reg0 (nt even, b0)
    // lanes 8-15:  rows n+0..7  @ k16+8    -> reg1 (nt even, b1)
    // lanes 16-23: rows n+8..15 @ k16      -> reg2 (nt odd, b0)
    // lanes 24-31: rows n+8..15 @ k16+8    -> reg3 (nt odd, b1)
    int b_row_off = (lane & 7) + ((lane >> 4) & 1) * 8;
    int b_col_off = (lane & 8) ? 8 : 0;

    for (int kt = 0; kt < NKCH; kt++) {
        CP_WAIT(0);
        __syncthreads();                          // stage kt ready; prior reads of other buffer done
        if (kt + 1 < NKCH) load_stage((kt + 1) & 1, (kt + 1) * GBK);

        uint32_t sb = ubase + (uint32_t)((kt & 1) * STAGE_ELEMS) * 2;
        uint32_t uAh = sb;
        uint32_t uAl = sb + TILE * 2;
        uint32_t uBh = sb + 2 * TILE * 2;
        uint32_t uBl = sb + 3 * TILE * 2;

        #pragma unroll
        for (int k16 = 0; k16 < GBK; k16 += 16) {
            uint32_t ah[2][4], al[2][4];
            #pragma unroll
            for (int mt = 0; mt < 2; mt++) {
                uint32_t off = (uint32_t)((wm + mt * 16 + (lane & 15)) * SROW + k16 + (lane >> 4) * 8) * 2;
                LDSM_X4(ah[mt], uAh + off);
                LDSM_X4(al[mt], uAl + off);
            }
            #pragma unroll
            for (int ntp = 0; ntp < 4; ntp++) {
                uint32_t boff = (uint32_t)((wn + ntp * 16 + b_row_off) * SROW + k16 + b_col_off) * 2;
                uint32_t b4h[4], b4l[4];
                LDSM_X4(b4h, uBh + boff);
                LDSM_X4(b4l, uBl + boff);
                #pragma unroll
                for (int sub = 0; sub < 2; sub++) {
                    int nt = ntp * 2 + sub;
                    uint32_t bh[2] = { b4h[sub * 2], b4h[sub * 2 + 1] };
                    uint32_t bl[2] = { b4l[sub * 2], b4l[sub * 2 + 1] };
                    #pragma unroll
                    for (int mt = 0; mt < 2; mt++) {
                        MMA_BF16(acc[mt][nt], ah[mt], bh);
                        MMA_BF16(acc[mt][nt], ah[mt], bl);
                        MMA_BF16(acc[mt][nt], al[mt], bh);
                    }
                }
            }
        }
    }

    #pragma unroll
    for (int mt = 0; mt < 2; mt++) {
        int r0 = row0 + wm + mt * 16 + (lane >> 2);
        #pragma unroll
        for (int nt = 0; nt < 8; nt++) {
            int c = col0 + wn + nt * 8 + (lane & 3) * 2;
            if (c < Nn) {
                if (r0 < M)
                    *(float2*)(C + (size_t)r0 * Nn + c) = make_float2(acc[mt][nt][0], acc[mt][nt][1]);
                if (r0 + 8 < M)
                    *(float2*)(C + (size_t)(r0 + 8) * Nn + c) = make_float2(acc[mt][nt][2], acc[mt][nt][3]);
            }
        }
    }
}

// ---------------- edge scatter, layer 1 (warp per edge, both heads, v4 red) -
__global__ void edge_scatter1() {
    int gw = (blockIdx.x * blockDim.x + threadIdx.x) >> 5;
    int lane = threadIdx.x & 31;
    if (gw >= E_ALL) return;
    int d = g_dst[gw], s = g_src[gw], ra = g_rA[gw], rb = g_rB[gw];
    float dot0 = g_d1[d] + g_s1[s] + g_r1[ra];
    float dot1 = g_d1[N_NODES + d] + g_s1[N_NODES + s] + g_r1[N_RELS + ra];
    if (rb >= 0) { dot0 += g_r1[rb]; dot1 += g_r1[N_RELS + rb]; }
    float lr0 = dot0 > 0.f ? dot0 : 0.2f * dot0;
    float lr1 = dot1 > 0.f ? dot1 : 0.2f * dot1;
    float ev0 = __expf(-lr0);
    float ev1 = __expf(-lr1);
    if (lane == 0) {
        red_add_f32(&g_rowsum1[d], ev0);
        red_add_f32(&g_rowsum1[N_NODES + d], ev1);
    }
    #pragma unroll
    for (int it = 0; it < 2; it++) {
        int q = lane + 32 * it;
        if (q < 50) {
            int h = (q < 25) ? 0 : 1;
            int c4 = (q < 25) ? q : q - 25;
            float ev = h ? ev1 : ev0;
            const float4* ps = (const float4*)(g_projA + (size_t)s * 600 + h * 200 + 100);
            const float4* rp = (const float4*)(g_relproj1 + (h * N_RELS + ra) * NHID);
            float4 v = ps[c4];
            float4 r = rp[c4];
            v.x += r.x; v.y += r.y; v.z += r.z; v.w += r.w;
            if (rb >= 0) {
                const float4* rp2 = (const float4*)(g_relproj1 + (h * N_RELS + rb) * NHID);
                float4 r2 = rp2[c4];
                v.x += r2.x; v.y += r2.y; v.z += r2.z; v.w += r2.w;
            }
            v.x *= ev; v.y *= ev; v.z *= ev; v.w *= ev;
            red_add_v4(g_acc1 + ((size_t)h * N_NODES + d) * NHID + c4 * 4, v);
        }
    }
}

// ---------------- combine layer-1 -> x1 split + layer-2 node scalars -------
__global__ void combine1() {
    int n = (blockIdx.x * blockDim.x + threadIdx.x) >> 5;
    int lane = threadIdx.x & 31;
    if (n >= N_NODES) return;
    float rs0 = g_rowsum1[n];
    float rs1 = g_rowsum1[N_NODES + n];
    bool h0 = rs0 != 0.f, h1 = rs1 != 0.f;
    float i0 = h0 ? 1.f / rs0 : 0.f;
    float i1 = h1 ? 1.f / rs1 : 0.f;
    const float* pd = g_projA + (size_t)n * 600;
    const float* a0 = g_acc1 + (size_t)n * NHID;
    const float* a1 = g_acc1 + ((size_t)N_NODES + n) * NHID;
    bf16* xh = g_x1h + (size_t)n * K_PAD;
    bf16* xl = g_x1l + (size_t)n * K_PAD;
    float d2 = 0.f, s2 = 0.f;
    #pragma unroll
    for (int t = 0; t < 4; t++) {
        int j = lane + 32 * t;
        if (j < NHID) {
            float hp0 = h0 ? pd[j] + a0[j] * i0 : 0.f;
            float hp1 = h1 ? pd[200 + j] + a1[j] * i1 : 0.f;
            float v0 = hp0 > 0.f ? hp0 : (__expf(hp0) - 1.f);
            float v1 = hp1 > 0.f ? hp1 : (__expf(hp1) - 1.f);
            bf16 hh, ll;
            split_bf16(v0, hh, ll); xh[j] = hh; xl[j] = ll;
            split_bf16(v1, hh, ll); xh[100 + j] = hh; xl[100 + j] = ll;
            d2 += v0 * g_w2[j]       + v1 * g_w2[100 + j];
            s2 += v0 * g_w2[200 + j] + v1 * g_w2[300 + j];
        }
    }
    int jp = 200 + lane;
    if (jp < K_PAD) { xh[jp] = __float2bfloat16_rn(0.f); xl[jp] = __float2bfloat16_rn(0.f); }
    d2 = warp_sum(d2); s2 = warp_sum(s2);
    if (lane == 0) { g_d2[n] = d2; g_s2[n] = s2; }
}

// ---------------- edge scatter, layer 2 (v4 red) ----------------
__global__ void edge_scatter2() {
    int gw = (blockIdx.x * blockDim.x + threadIdx.x) >> 5;
    int lane = threadIdx.x & 31;
    if (gw >= E_ALL) return;
    int d = g_dst[gw], s = g_src[gw], ra = g_rA[gw], rb = g_rB[gw];
    float dot = g_d2[d] + g_s2[s] + g_r2[ra];
    if (rb >= 0) dot += g_r2[rb];
    float lr = dot > 0.f ? dot : 0.2f * dot;
    float ev = __expf(-lr);
    if (lane == 0) red_add_f32(&g_rowsum2[d], ev);
    const float4* ps = (const float4*)(g_proj2 + (size_t)s * 400 + 200);
    const float4* rp = (const float4*)(g_relproj2 + (size_t)ra * DIM);
    const float4* rpb = (rb >= 0) ? (const float4*)(g_relproj2 + (size_t)rb * DIM) : nullptr;
    float* accrow = g_acc2 + (size_t)d * DIM;
    #pragma unroll
    for (int it = 0; it < 2; it++) {
        int q = lane + 32 * it;
        if (q < 50) {
            float4 v = ps[q];
            float4 r = rp[q];
            v.x += r.x; v.y += r.y; v.z += r.z; v.w += r.w;
            if (rpb) {
                float4 r2 = rpb[q];
                v.x += r2.x; v.y += r2.y; v.z += r2.z; v.w += r2.w;
            }
            v.x *= ev; v.y *= ev; v.z *= ev; v.w *= ev;
            red_add_v4(accrow + q * 4, v);
        }
    }
}

// ---------------- finalize: out_ent = l2norm(entlin + mask*elu(hp)) --------
__global__ void finalize(float* __restrict__ out) {
    int n = (blockIdx.x * blockDim.x + threadIdx.x) >> 5;
    int lane = threadIdx.x & 31;
    if (n >= N_NODES) return;
    float rs = g_rowsum2[n];
    bool has = rs != 0.f;
    float iS = has ? 1.f / rs : 0.f;
    float mk = g_mask[n];
    const float* pd = g_proj2 + (size_t)n * 400;
    const float* lin = g_projA + (size_t)n * 600 + 400;
    const float* acc = g_acc2 + (size_t)n * DIM;
    float v[7];
    float ss = 0.f;
    #pragma unroll
    for (int t = 0; t < 7; t++) {
        int j = lane + 32 * t;
        float val = 0.f;
        if (j < DIM) {
            float hp = has ? pd[j] + acc[j] * iS : 0.f;
            float el = hp > 0.f ? hp : (expf(hp) - 1.f);
            val = lin[j] + mk * el;
            ss += val * val;
        }
        v[t] = val;
    }
    ss = warp_sum(ss);
    float sc = 1.f / fmaxf(sqrtf(ss), 1e-12f);
    #pragma unroll
    for (int t = 0; t < 7; t++) {
        int j = lane + 32 * t;
        if (j < DIM) out[(size_t)n * DIM + j] = v[t] * sc;
    }
}

__global__ void copy_tail(float* __restrict__ out) {
    int i = blockIdx.x * blockDim.x + threadIdx.x;
    const size_t base = (size_t)N_NODES * DIM;
    if (i < N_RELS * DIM) out[base + i] = g_outrel[i];
    if (i < N_NODES) out[base + N_RELS * DIM + i] = g_mask[i];
}

// ---------------- launch ----------------
extern "C" void kernel_launch(void* const* d_in, const int* in_sizes, int n_in,
                              void* d_out, int out_size) {
    const float* ent   = (const float*)d_in[0];
    const float* rel   = (const float*)d_in[1];
    const float* W_ent = (const float*)d_in[2];
    const float* W_gat = (const float*)d_in[3];
    const float* a_h   = (const float*)d_in[4];
    const float* a2_h  = (const float*)d_in[5];
    const float* a_o   = (const float*)d_in[6];
    const float* a2_o  = (const float*)d_in[7];
    const int*   batch = (const int*)d_in[8];
    const int*   elist = (const int*)d_in[9];
    const int*   etype = (const int*)d_in[10];
    const int*   nhop  = (const int*)d_in[11];
    float* out = (float*)d_out;
    int n_batch = in_sizes[8];

    const int PREP_N = (600 * K_PAD > E_ALL) ? 600 * K_PAD : E_ALL;

    cudaFuncSetAttribute(gemm_bf16s<0>, cudaFuncAttributeMaxDynamicSharedMemorySize, SMEM_BYTES);
    cudaFuncSetAttribute(gemm_bf16s<1>, cudaFuncAttributeMaxDynamicSharedMemorySize, SMEM_BYTES);

    fold_w<<<(N_NODES + 255) / 256, 256>>>(a_h, a2_h, a_o, a2_o);                       // 0
    prep<<<(PREP_N + 255) / 256, 256>>>(a_h, a_o, W_ent, elist, etype, nhop, batch, n_batch); // 1
    l2norm_conv<<<(N_NODES * 32 + 255) / 256, 256>>>(ent);                              // 2

    {   // 3 — projA = [x@Bcat1^T | x@W_ent]  (profiled launch slot)
        dim3 grid((600 + GBN - 1) / GBN, (N_NODES + GBM - 1) / GBM);
        gemm_bf16s<0><<<grid, 256, SMEM_BYTES>>>();
    }

    zero_all<<<2048, 256>>>();                                                          // 4
    relA<<<(NHEADS * N_RELS * NHID + 255) / 256, 256>>>(rel, a_h, W_gat);               // 5
    relB<<<(N_RELS * DIM + 255) / 256, 256>>>(a_o);                                     // 6

    {
        dim3 grid((E_ALL + 7) / 8, 1);
        edge_scatter1<<<grid, 256>>>();                                                 // 7
    }
    combine1<<<(N_NODES * 32 + 255) / 256, 256>>>();                                    // 8

    {   // proj2 = x1 @ Bcat2^T
        dim3 grid((400 + GBN - 1) / GBN, (N_NODES + GBM - 1) / GBM);
        gemm_bf16s<1><<<grid, 256, SMEM_BYTES>>>();                                     // 9
    }

    {
        dim3 grid((E_ALL + 7) / 8, 1);
        edge_scatter2<<<grid, 256>>>();                                                 // 10
    }

    finalize<<<(N_NODES * 32 + 255) / 256, 256>>>(out);                                 // 11
    copy_tail<<<(N_RELS * DIM + 255) / 256, 256>>>(out);                                // 12
}